// round 13
// baseline (speedup 1.0000x reference)
#include <cuda_runtime.h>
#include <cuda_bf16.h>
#include <cstdint>

// Problem dims (fixed for this problem instance)
#define NR   8192   // rows (nodes)
#define DIN  512    // input feature dim
#define DOUT 128    // output feature dim

// ---------------- scratch (static device globals; no allocation) ----------------
__device__ __align__(16) __nv_bfloat16 g_hw1b[DIN * DOUT]; // proj(expmap0(lin_weight))^T, bf16 [k][n]
__device__ __align__(16) float g_hw2[DOUT * DOUT];  // proj(expmap0(agg_weight))
__device__ __align__(16) float g_hb[DOUT];          // proj(expmap0(lin_bias))
__device__ float g_hb2s;                            // sum hb^2
__device__ float g_b2s;                             // sum agg_bias^2
__device__ __align__(16) float g_h[NR * DOUT];      // hyp_linear output
__device__ float g_hn[NR];                          // ||h_i|| (clamped)
__device__ __align__(16) __nv_bfloat16 g_supb[NR * DOUT];  // support, bf16, node-major

// ---------------- baseline-PTX helpers (no sm_103a-only instructions) ----------------
__device__ __forceinline__ uint32_t smem_u32(const void* p) {
    uint32_t a;
    asm("{ .reg .u64 t; cvta.to.shared.u64 t, %1; cvt.u32.u64 %0, t; }" : "=r"(a) : "l"(p));
    return a;
}
__device__ __forceinline__ uint32_t pack_bf16(float lo, float hi) {
    uint32_t r;
    asm("cvt.rn.bf16x2.f32 %0, %1, %2;" : "=r"(r) : "f"(hi), "f"(lo));
    return r;
}
__device__ __forceinline__ void cp_async16(uint32_t dst_smem, const void* src) {
    asm volatile("cp.async.cg.shared.global [%0], [%1], 16;" :: "r"(dst_smem), "l"(src) : "memory");
}
#define CP_COMMIT() asm volatile("cp.async.commit_group;" ::: "memory")
#define CP_WAIT0()  asm volatile("cp.async.wait_group 0;" ::: "memory")

#define LDSM_X4(r0, r1, r2, r3, addr) \
    asm volatile("ldmatrix.sync.aligned.m8n8.x4.shared.b16 {%0,%1,%2,%3}, [%4];" \
        : "=r"(r0), "=r"(r1), "=r"(r2), "=r"(r3) : "r"(addr))
#define LDSM_X4T(r0, r1, r2, r3, addr) \
    asm volatile("ldmatrix.sync.aligned.m8n8.x4.trans.shared.b16 {%0,%1,%2,%3}, [%4];" \
        : "=r"(r0), "=r"(r1), "=r"(r2), "=r"(r3) : "r"(addr))

// m16n8k16 bf16 MMA (compute_80 baseline feature)
__device__ __forceinline__ void mma_bf16(float* d,
                                         uint32_t a0, uint32_t a1, uint32_t a2, uint32_t a3,
                                         uint32_t b0, uint32_t b1) {
    asm volatile(
        "mma.sync.aligned.m16n8k16.row.col.f32.bf16.bf16.f32 "
        "{%0,%1,%2,%3}, {%4,%5,%6,%7}, {%8,%9}, {%0,%1,%2,%3};"
        : "+f"(d[0]), "+f"(d[1]), "+f"(d[2]), "+f"(d[3])
        : "r"(a0), "r"(a1), "r"(a2), "r"(a3), "r"(b0), "r"(b1));
}

// ---------------- helpers ----------------
__device__ __forceinline__ float blockReduceSum128(float v, float* sred) {
    #pragma unroll
    for (int o = 16; o > 0; o >>= 1) v += __shfl_xor_sync(0xffffffffu, v, o);
    int w = threadIdx.x >> 5;
    if ((threadIdx.x & 31) == 0) sred[w] = v;
    __syncthreads();
    float r = sred[0] + sred[1] + sred[2] + sred[3];
    __syncthreads();
    return r;
}

// ---------------- K0: weight prep: hw = proj(expmap0(W,c),c) ----------------
__global__ __launch_bounds__(128) void k_prep(
    const float* __restrict__ lw, const float* __restrict__ lb,
    const float* __restrict__ aw, const float* __restrict__ ab,
    const float* __restrict__ cp)
{
    __shared__ float sred[4];
    const float c    = cp[0];
    const float sc   = sqrtf(c);
    const float maxn = (1.0f - 4e-3f) / sc;
    const int b = blockIdx.x, t = threadIdx.x;

    if (b < DOUT) {                       // hw1 rows (len 512) -> bf16 transposed [k][n]
        const float* u = lw + b * DIN;
        float ss = 0.f;
        #pragma unroll
        for (int i = t; i < DIN; i += 128) { float v = u[i]; ss += v * v; }
        ss = blockReduceSum128(ss, sred);
        float un = fmaxf(sqrtf(ss), 1e-15f);
        float f  = tanhf(sc * un) / (sc * un);
        float vn = fmaxf(sqrtf(f * f * ss), 1e-15f);
        float coef = f * (vn > maxn ? maxn / vn : 1.0f);
        for (int i = t; i < DIN; i += 128)
            g_hw1b[(size_t)i * DOUT + b] = __float2bfloat16(coef * u[i]);
    } else if (b < 2 * DOUT) {            // hw2 rows (len 128)
        int r = b - DOUT;
        const float* u = aw + r * DOUT;
        float x = u[t];
        float ss = blockReduceSum128(x * x, sred);
        float un = fmaxf(sqrtf(ss), 1e-15f);
        float f  = tanhf(sc * un) / (sc * un);
        float vn = fmaxf(sqrtf(f * f * ss), 1e-15f);
        float coef = f * (vn > maxn ? maxn / vn : 1.0f);
        g_hw2[r * DOUT + t] = coef * x;
    } else {                              // hb + bias sumsq scalars
        float x = lb[t];
        float ss = blockReduceSum128(x * x, sred);
        float un = fmaxf(sqrtf(ss), 1e-15f);
        float f  = tanhf(sc * un) / (sc * un);
        float vn = fmaxf(sqrtf(f * f * ss), 1e-15f);
        float coef = f * (vn > maxn ? maxn / vn : 1.0f);
        g_hb[t] = coef * x;
        if (t == 0) g_hb2s = coef * coef * ss;
        float y = ab[t];
        float s2 = blockReduceSum128(y * y, sred);
        if (t == 0) g_b2s = s2;
    }
}

// ============ bf16-MMA tile constants (K1, K3: M=64 x N=128, KC=64) ============
// A smem [m=64][k=64] bf16, row stride 144 B -> ldmatrix conflict-free.
// B smem [k=64][n=128] bf16, row stride 272 B -> ldmatrix.trans conflict-free.
#define KC      64
#define ASTR_B  144
#define BSTR_B  272
#define A_BYTES (64 * ASTR_B)   // 9216
#define B_BYTES (KC * BSTR_B)   // 17408
#define DYN_SMEM (2 * (A_BYTES + B_BYTES))  // 53248

// ---------------- K1: h = hyp_linear(x,...) bf16 mma.sync ----------------
__global__ __launch_bounds__(256) void k_lin_mma(
    const float* __restrict__ x, const float* __restrict__ cp)
{
    extern __shared__ __align__(16) char dsm[];
    char* Ab0 = dsm;
    char* Bb0 = dsm + 2 * A_BYTES;
    __shared__ float bv[128];
    __shared__ float arow[64];
    __shared__ float sredS[64][2][3];

    const int t = threadIdx.x;
    const int w = t >> 5, l = t & 31;
    const int mb = (w & 3) * 16;
    const int nhalf = w >> 2;
    const int rowbase = blockIdx.x * 64;
    const float c  = cp[0];
    const float sc = sqrtf(c);

    if (t < 128) bv[t] = g_hb[t];

    const int arI = t >> 2, aq = t & 3;   // A loader: 4 threads/row, 16 floats each
    const float4* ap = (const float4*)(x + (size_t)(rowbase + arI) * DIN);
    const int bkr = t >> 2, bq = t & 3;   // B loader: 4 threads/k-row, 64 B each

    const uint32_t abase = smem_u32(Ab0);
    const uint32_t bbase = smem_u32(Bb0);

    float acc[8][4];
    #pragma unroll
    for (int i = 0; i < 8; i++)
        #pragma unroll
        for (int j = 0; j < 4; j++) acc[i][j] = 0.f;

    float asq = 0.f;
    float4 la[4];

    const int NCH = DIN / KC;  // 8

    // prologue: chunk 0
    #pragma unroll
    for (int i = 0; i < 4; i++) la[i] = ap[aq * 4 + i];
    #pragma unroll
    for (int i = 0; i < 2; i++) {
        float4 v0 = la[2 * i], v1 = la[2 * i + 1];
        asq += v0.x*v0.x + v0.y*v0.y + v0.z*v0.z + v0.w*v0.w
             + v1.x*v1.x + v1.y*v1.y + v1.z*v1.z + v1.w*v1.w;
        uint4 u = make_uint4(pack_bf16(v0.x, v0.y), pack_bf16(v0.z, v0.w),
                             pack_bf16(v1.x, v1.y), pack_bf16(v1.z, v1.w));
        *(uint4*)&Ab0[arI * ASTR_B + aq * 32 + i * 16] = u;
    }
    #pragma unroll
    for (int i = 0; i < 4; i++)
        cp_async16(bbase + (uint32_t)(bkr * BSTR_B + bq * 64 + i * 16),
                   (const char*)g_hw1b + ((size_t)bkr * DOUT + bq * 32 + i * 8) * 2);
    CP_COMMIT();
    CP_WAIT0();
    __syncthreads();

    for (int ck = 0; ck < NCH; ++ck) {
        const int cur = ck & 1, nxt = cur ^ 1;
        const bool more = (ck + 1 < NCH);
        if (more) {
            #pragma unroll
            for (int i = 0; i < 4; i++) la[i] = ap[(ck + 1) * 16 + aq * 4 + i];
            #pragma unroll
            for (int i = 0; i < 4; i++)
                cp_async16(bbase + (uint32_t)(nxt * B_BYTES + bkr * BSTR_B + bq * 64 + i * 16),
                           (const char*)g_hw1b + ((size_t)((ck + 1) * KC + bkr) * DOUT + bq * 32 + i * 8) * 2);
            CP_COMMIT();
        }
        {
            const uint32_t aT = abase + (uint32_t)cur * A_BYTES;
            const uint32_t bT = bbase + (uint32_t)cur * B_BYTES;
            #pragma unroll
            for (int ks = 0; ks < 4; ks++) {
                uint32_t a0, a1, a2, a3;
                uint32_t aaddr = aT + (uint32_t)((mb + (l & 15)) * ASTR_B + ks * 32 + (l >> 4) * 16);
                LDSM_X4(a0, a1, a2, a3, aaddr);
                #pragma unroll
                for (int p = 0; p < 4; p++) {
                    uint32_t b0, b1, b2, b3;
                    uint32_t baddr = bT + (uint32_t)((ks * 16 + (l & 15)) * BSTR_B
                                   + nhalf * 128 + (2 * p + (l >> 4)) * 16);
                    LDSM_X4T(b0, b1, b2, b3, baddr);
                    mma_bf16(acc[2 * p],     a0, a1, a2, a3, b0, b1);
                    mma_bf16(acc[2 * p + 1], a0, a1, a2, a3, b2, b3);
                }
            }
        }
        if (more) {
            #pragma unroll
            for (int i = 0; i < 2; i++) {
                float4 v0 = la[2 * i], v1 = la[2 * i + 1];
                asq += v0.x*v0.x + v0.y*v0.y + v0.z*v0.z + v0.w*v0.w
                     + v1.x*v1.x + v1.y*v1.y + v1.z*v1.z + v1.w*v1.w;
                uint4 u = make_uint4(pack_bf16(v0.x, v0.y), pack_bf16(v0.z, v0.w),
                                     pack_bf16(v1.x, v1.y), pack_bf16(v1.z, v1.w));
                *(uint4*)&Ab0[nxt * A_BYTES + arI * ASTR_B + aq * 32 + i * 16] = u;
            }
            CP_WAIT0();
        }
        __syncthreads();
    }

    // x row sumsq: combine 4 loader threads per row
    asq += __shfl_xor_sync(0xffffffffu, asq, 1);
    asq += __shfl_xor_sync(0xffffffffu, asq, 2);
    if ((t & 3) == 0) arow[arI] = asq;
    __syncthreads();

    // fragment-domain hyp_linear epilogue
    float S1[2] = {0.f, 0.f}, S2[2] = {0.f, 0.f}, S3[2] = {0.f, 0.f};
    #pragma unroll
    for (int nt = 0; nt < 8; nt++) {
        const int col = nhalf * 64 + nt * 8 + 2 * (l & 3);
        const float b0 = bv[col], b1 = bv[col + 1];
        float c0 = acc[nt][0], c1 = acc[nt][1], c2 = acc[nt][2], c3 = acc[nt][3];
        S1[0] += c0*c0 + c1*c1;  S2[0] += fabsf(c0) + fabsf(c1);  S3[0] += c0*b0 + c1*b1;
        S1[1] += c2*c2 + c3*c3;  S2[1] += fabsf(c2) + fabsf(c3);  S3[1] += c2*b0 + c3*b1;
    }
    #pragma unroll
    for (int r = 0; r < 2; r++) {
        S1[r] += __shfl_xor_sync(0xffffffffu, S1[r], 1);
        S1[r] += __shfl_xor_sync(0xffffffffu, S1[r], 2);
        S2[r] += __shfl_xor_sync(0xffffffffu, S2[r], 1);
        S2[r] += __shfl_xor_sync(0xffffffffu, S2[r], 2);
        S3[r] += __shfl_xor_sync(0xffffffffu, S3[r], 1);
        S3[r] += __shfl_xor_sync(0xffffffffu, S3[r], 2);
    }
    if ((l & 3) == 0) {
        const int r0 = mb + (l >> 2);
        sredS[r0][nhalf][0] = S1[0]; sredS[r0][nhalf][1] = S2[0]; sredS[r0][nhalf][2] = S3[0];
        sredS[r0 + 8][nhalf][0] = S1[1]; sredS[r0 + 8][nhalf][1] = S2[1]; sredS[r0 + 8][nhalf][2] = S3[1];
    }
    __syncthreads();

    float Pr[2], Qr[2];
    const float y2 = g_hb2s;
    const float maxn = (1.0f - 4e-3f) / sc;
    #pragma unroll
    for (int r = 0; r < 2; r++) {
        const int rl = mb + (l >> 2) + r * 8;
        float S1t = sredS[rl][0][0] + sredS[rl][1][0];
        float S2t = sredS[rl][0][1] + sredS[rl][1][1];
        float S3t = sredS[rl][0][2] + sredS[rl][1][2];
        float xn  = fmaxf(sqrtf(arow[rl]), 1e-15f);
        float mxn = fmaxf(sqrtf(S1t), 1e-15f);
        float at  = atanhf(fminf(sc * xn, 1.0f - 1e-7f));
        float s   = tanhf(mxn / xn * at) / (mxn * sc);
        if (S2t == 0.f) s = 0.f;
        float rn = fmaxf(sqrtf(s * s * S1t), 1e-15f);
        if (rn > maxn) s *= maxn / rn;          // proj before mobius_add
        float x2 = s * s * S1t;
        float xy = s * S3t;
        float Aa = 1.0f + 2.0f * c * xy + c * y2;
        float Bb2 = 1.0f - c * x2;
        float den = fmaxf(1.0f + 2.0f * c * xy + c * c * x2 * y2, 1e-15f);
        float P = Aa * s / den, Q = Bb2 / den;
        float h2 = P * P * S1t + 2.0f * P * Q * S3t + Q * Q * y2;
        float hn = fmaxf(sqrtf(h2), 1e-15f);
        if (hn > maxn) { float g = maxn / hn; P *= g; Q *= g; hn = maxn; }
        Pr[r] = P; Qr[r] = Q;
        if (((l & 3) == 0) && nhalf == 0) g_hn[rowbase + rl] = hn;
    }

    const int g0 = rowbase + mb + (l >> 2);
    #pragma unroll
    for (int nt = 0; nt < 8; nt++) {
        const int col = nhalf * 64 + nt * 8 + 2 * (l & 3);
        *(float2*)&g_h[(size_t)g0 * DOUT + col] =
            make_float2(Pr[0] * acc[nt][0] + Qr[0] * bv[col],
                        Pr[0] * acc[nt][1] + Qr[0] * bv[col + 1]);
        *(float2*)&g_h[(size_t)(g0 + 8) * DOUT + col] =
            make_float2(Pr[1] * acc[nt][2] + Qr[1] * bv[col],
                        Pr[1] * acc[nt][3] + Qr[1] * bv[col + 1]);
    }
}

// ============ FFMA GEMM tile config (K2) ============
#define BK  32
#define BMP 68
#define BN  128

// ---------------- K2: support = mobius_matvec(hw2, h) fused GEMM -> bf16 ----------------
__global__ __launch_bounds__(128) void k_sup_gemm(const float* __restrict__ cp) {
    __shared__ __align__(16) float pool[BK * BMP + BK * BN];
    __shared__ float par[64];
    float* As = pool;
    float* Bs = pool + BK * BMP;

    const int t = threadIdx.x;
    const int rowbase = blockIdx.x * 64;
    const float c  = cp[0];
    const float sc = sqrtf(c);

    const int tr = t >> 4, tc = t & 15;
    const int ar = t >> 3, ac = (t & 7) * 4;

    float acc[8][8];
    #pragma unroll
    for (int i = 0; i < 8; i++)
        #pragma unroll
        for (int j = 0; j < 8; j++) acc[i][j] = 0.f;

    float4 la[4], lb8[8];
    #pragma unroll
    for (int p = 0; p < 4; p++)
        la[p] = *(const float4*)&g_h[(size_t)(rowbase + p * 16 + ar) * DOUT + ac];
    #pragma unroll
    for (int f = 0; f < 8; f++)
        lb8[f] = *(const float4*)&g_hw2[t * DOUT + f * 4];

    const int ITERS = DOUT / BK;  // 4
    for (int it = 0; it < ITERS; ++it) {
        __syncthreads();
        #pragma unroll
        for (int p = 0; p < 4; p++) {
            float4 v = la[p]; int r = p * 16 + ar;
            As[(ac + 0) * BMP + r] = v.x; As[(ac + 1) * BMP + r] = v.y;
            As[(ac + 2) * BMP + r] = v.z; As[(ac + 3) * BMP + r] = v.w;
        }
        #pragma unroll
        for (int f = 0; f < 8; f++) {
            float4 v = lb8[f];
            Bs[(f * 4 + 0) * BN + t] = v.x; Bs[(f * 4 + 1) * BN + t] = v.y;
            Bs[(f * 4 + 2) * BN + t] = v.z; Bs[(f * 4 + 3) * BN + t] = v.w;
        }
        __syncthreads();
        if (it + 1 < ITERS) {
            int kt = (it + 1) * BK;
            #pragma unroll
            for (int p = 0; p < 4; p++)
                la[p] = *(const float4*)&g_h[(size_t)(rowbase + p * 16 + ar) * DOUT + kt + ac];
            #pragma unroll
            for (int f = 0; f < 8; f++)
                lb8[f] = *(const float4*)&g_hw2[t * DOUT + kt + f * 4];
        }
        #pragma unroll
        for (int kk = 0; kk < BK; kk++) {
            float4 a0 = *(const float4*)&As[kk * BMP + tr * 8];
            float4 a1 = *(const float4*)&As[kk * BMP + tr * 8 + 4];
            float4 b0 = *(const float4*)&Bs[kk * BN + tc * 4];
            float4 b1 = *(const float4*)&Bs[kk * BN + tc * 4 + 64];
            float av[8] = {a0.x,a0.y,a0.z,a0.w,a1.x,a1.y,a1.z,a1.w};
            float bv[8] = {b0.x,b0.y,b0.z,b0.w,b1.x,b1.y,b1.z,b1.w};
            #pragma unroll
            for (int i = 0; i < 8; i++)
                #pragma unroll
                for (int j = 0; j < 8; j++) acc[i][j] += av[i] * bv[j];
        }
    }
    __syncthreads();

    float* red = pool;  // [64][16][2]
    #pragma unroll
    for (int i = 0; i < 8; i++) {
        int r = tr * 8 + i;
        float p1 = 0.f, p2 = 0.f;
        #pragma unroll
        for (int j = 0; j < 8; j++) { float v = acc[i][j]; p1 += v * v; p2 += fabsf(v); }
        red[(r * 16 + tc) * 2 + 0] = p1;
        red[(r * 16 + tc) * 2 + 1] = p2;
    }
    __syncthreads();
    if (t < 64) {
        float S1 = 0.f, S2 = 0.f;
        #pragma unroll
        for (int q = 0; q < 16; q++) {
            S1 += red[(t * 16 + q) * 2 + 0];
            S2 += red[(t * 16 + q) * 2 + 1];
        }
        float hn  = g_hn[rowbase + t];
        float mxn = fmaxf(sqrtf(S1), 1e-15f);
        float at  = atanhf(fminf(sc * hn, 1.0f - 1e-7f));
        float s   = tanhf(mxn / hn * at) / (mxn * sc);
        if (S2 == 0.f) s = 0.f;
        par[t] = s;
    }
    __syncthreads();
    #pragma unroll
    for (int i = 0; i < 8; i++) {
        int r = tr * 8 + i;
        float s = par[r];
        uint32_t u0 = pack_bf16(s * acc[i][0], s * acc[i][1]);
        uint32_t u1 = pack_bf16(s * acc[i][2], s * acc[i][3]);
        uint32_t u2 = pack_bf16(s * acc[i][4], s * acc[i][5]);
        uint32_t u3 = pack_bf16(s * acc[i][6], s * acc[i][7]);
        *(uint2*)&g_supb[(size_t)(rowbase + r) * DOUT + tc * 4]      = make_uint2(u0, u1);
        *(uint2*)&g_supb[(size_t)(rowbase + r) * DOUT + 64 + tc * 4] = make_uint2(u2, u3);
    }
}

// ---------------- K3: bf16 mma.sync adj@sup + fused hyperbolic epilogue ----------------
// 128 CTAs x 256 threads (8 warps). CTA: M=64 x N=128, K=8192 chunked by KC=64.
// A-prefetch distance 2: at chunk ck we ISSUE LDGs for ck+2 while STS consumes the
// registers loaded at ck-1 -> load-to-use window = ~2 chunk periods (covers DRAM lat).
__global__ __launch_bounds__(256) void k_agg_mma(
    const float* __restrict__ adj, const float* __restrict__ bias,
    const float* __restrict__ cp, float* __restrict__ out)
{
    extern __shared__ __align__(16) char dsm[];
    char* Ab0 = dsm;
    char* Bb0 = dsm + 2 * A_BYTES;
    __shared__ float bv[128];
    __shared__ float arow[64];
    __shared__ float sredS[64][2][3];
    __shared__ float sredQ[64][2];

    const int t = threadIdx.x;
    const int w = t >> 5, l = t & 31;
    const int mb = (w & 3) * 16;
    const int nhalf = w >> 2;
    const int rowbase = blockIdx.x * 64;
    const float c  = cp[0];
    const float sc = sqrtf(c);

    if (t < 128) bv[t] = bias[t];

    const int arI = t >> 2, aq = t & 3;   // A loader: 4 threads/row, 16 floats each
    const float4* ap = (const float4*)(adj + (size_t)(rowbase + arI) * NR);
    const int bkr = t >> 2, bq = t & 3;   // B loader: 4 threads/k-row, 64 B each

    const uint32_t abase = smem_u32(Ab0);
    const uint32_t bbase = smem_u32(Bb0);

    float acc[8][4];
    #pragma unroll
    for (int i = 0; i < 8; i++)
        #pragma unroll
        for (int j = 0; j < 4; j++) acc[i][j] = 0.f;

    float asq = 0.f;
    float4 laA[4], laB[4];   // two register sets for prefetch distance 2

    const int NCH = NR / KC;  // 128

    // -------- prologue --------
    // chunk 0 -> A smem buf0 directly
    #pragma unroll
    for (int i = 0; i < 4; i++) laA[i] = ap[aq * 4 + i];
    #pragma unroll
    for (int i = 0; i < 2; i++) {
        float4 v0 = laA[2 * i], v1 = laA[2 * i + 1];
        asq += v0.x*v0.x + v0.y*v0.y + v0.z*v0.z + v0.w*v0.w
             + v1.x*v1.x + v1.y*v1.y + v1.z*v1.z + v1.w*v1.w;
        uint4 u = make_uint4(pack_bf16(v0.x, v0.y), pack_bf16(v0.z, v0.w),
                             pack_bf16(v1.x, v1.y), pack_bf16(v1.z, v1.w));
        *(uint4*)&Ab0[arI * ASTR_B + aq * 32 + i * 16] = u;
    }
    // chunk 1 -> laA registers (will be STS'd at end of iter 0)
    #pragma unroll
    for (int i = 0; i < 4; i++) laA[i] = ap[16 + aq * 4 + i];
    // B chunk 0 -> B smem buf0
    #pragma unroll
    for (int i = 0; i < 4; i++)
        cp_async16(bbase + (uint32_t)(bkr * BSTR_B + bq * 64 + i * 16),
                   (const char*)g_supb + ((size_t)bkr * DOUT + bq * 32 + i * 8) * 2);
    CP_COMMIT();
    CP_WAIT0();
    __syncthreads();

    // -------- main loop, unrolled x2 over (SA holds chunk ck+1, SB gets chunk ck+2) --------
    auto step = [&](int ck, float4* SA, float4* SB) {
        const int cur = ck & 1, nxt = cur ^ 1;
        if (ck + 2 < NCH) {   // issue LDGs for chunk ck+2 (consumed 2 iterations later)
            #pragma unroll
            for (int i = 0; i < 4; i++) SB[i] = ap[(ck + 2) * 16 + aq * 4 + i];
        }
        const bool moreB = (ck + 1 < NCH);
        if (moreB) {
            #pragma unroll
            for (int i = 0; i < 4; i++)
                cp_async16(bbase + (uint32_t)(nxt * B_BYTES + bkr * BSTR_B + bq * 64 + i * 16),
                           (const char*)g_supb + ((size_t)((ck + 1) * KC + bkr) * DOUT + bq * 32 + i * 8) * 2);
            CP_COMMIT();
        }
        {
            const uint32_t aT = abase + (uint32_t)cur * A_BYTES;
            const uint32_t bT = bbase + (uint32_t)cur * B_BYTES;
            #pragma unroll
            for (int ks = 0; ks < 4; ks++) {
                uint32_t a0, a1, a2, a3;
                uint32_t aaddr = aT + (uint32_t)((mb + (l & 15)) * ASTR_B + ks * 32 + (l >> 4) * 16);
                LDSM_X4(a0, a1, a2, a3, aaddr);
                #pragma unroll
                for (int p = 0; p < 4; p++) {
                    uint32_t b0, b1, b2, b3;
                    uint32_t baddr = bT + (uint32_t)((ks * 16 + (l & 15)) * BSTR_B
                                   + nhalf * 128 + (2 * p + (l >> 4)) * 16);
                    LDSM_X4T(b0, b1, b2, b3, baddr);
                    mma_bf16(acc[2 * p],     a0, a1, a2, a3, b0, b1);
                    mma_bf16(acc[2 * p + 1], a0, a1, a2, a3, b2, b3);
                }
            }
        }
        if (moreB) {   // STS chunk ck+1 (loaded ~2 iterations ago)
            #pragma unroll
            for (int i = 0; i < 2; i++) {
                float4 v0 = SA[2 * i], v1 = SA[2 * i + 1];
                asq += v0.x*v0.x + v0.y*v0.y + v0.z*v0.z + v0.w*v0.w
                     + v1.x*v1.x + v1.y*v1.y + v1.z*v1.z + v1.w*v1.w;
                uint4 u = make_uint4(pack_bf16(v0.x, v0.y), pack_bf16(v0.z, v0.w),
                                     pack_bf16(v1.x, v1.y), pack_bf16(v1.z, v1.w));
                *(uint4*)&Ab0[nxt * A_BYTES + arI * ASTR_B + aq * 32 + i * 16] = u;
            }
            CP_WAIT0();
        }
        __syncthreads();
    };
    for (int ck = 0; ck < NCH; ck += 2) {
        step(ck,     laA, laB);
        step(ck + 1, laB, laA);
    }

    // adj row sumsq: combine 4 loader threads per row
    asq += __shfl_xor_sync(0xffffffffu, asq, 1);
    asq += __shfl_xor_sync(0xffffffffu, asq, 2);
    if ((t & 3) == 0) arow[arI] = asq;
    __syncthreads();

    // -------- fragment-domain hyperbolic epilogue --------
    float S1[2] = {0.f, 0.f}, S2[2] = {0.f, 0.f}, S3[2] = {0.f, 0.f};
    #pragma unroll
    for (int nt = 0; nt < 8; nt++) {
        const int col = nhalf * 64 + nt * 8 + 2 * (l & 3);
        const float b0 = bv[col], b1 = bv[col + 1];
        float c0 = acc[nt][0], c1 = acc[nt][1], c2 = acc[nt][2], c3 = acc[nt][3];
        S1[0] += c0*c0 + c1*c1;  S2[0] += fabsf(c0) + fabsf(c1);  S3[0] += c0*b0 + c1*b1;
        S1[1] += c2*c2 + c3*c3;  S2[1] += fabsf(c2) + fabsf(c3);  S3[1] += c2*b0 + c3*b1;
    }
    #pragma unroll
    for (int r = 0; r < 2; r++) {
        S1[r] += __shfl_xor_sync(0xffffffffu, S1[r], 1);
        S1[r] += __shfl_xor_sync(0xffffffffu, S1[r], 2);
        S2[r] += __shfl_xor_sync(0xffffffffu, S2[r], 1);
        S2[r] += __shfl_xor_sync(0xffffffffu, S2[r], 2);
        S3[r] += __shfl_xor_sync(0xffffffffu, S3[r], 1);
        S3[r] += __shfl_xor_sync(0xffffffffu, S3[r], 2);
    }
    if ((l & 3) == 0) {
        const int r0 = mb + (l >> 2);
        sredS[r0][nhalf][0] = S1[0]; sredS[r0][nhalf][1] = S2[0]; sredS[r0][nhalf][2] = S3[0];
        sredS[r0 + 8][nhalf][0] = S1[1]; sredS[r0 + 8][nhalf][1] = S2[1]; sredS[r0 + 8][nhalf][2] = S3[1];
    }
    __syncthreads();

    float Pr[2], Qr[2], Lr[2];
    const float y2 = g_b2s;
    const float maxn = (1.0f - 4e-3f) / sc;
    #pragma unroll
    for (int r = 0; r < 2; r++) {
        const int rl = mb + (l >> 2) + r * 8;
        float S1t = sredS[rl][0][0] + sredS[rl][1][0];
        float S2t = sredS[rl][0][1] + sredS[rl][1][1];
        float S3t = sredS[rl][0][2] + sredS[rl][1][2];
        float an  = fmaxf(sqrtf(arow[rl]), 1e-15f);
        float mxn = fmaxf(sqrtf(S1t), 1e-15f);
        float at  = atanhf(fminf(sc * an, 1.0f - 1e-7f));
        float s   = tanhf(mxn / an * at) / (mxn * sc);
        if (S2t == 0.f) s = 0.f;
        float x2 = s * s * S1t;
        float xy = s * S3t;
        float Aa = 1.0f + 2.0f * c * xy + c * y2;
        float Bb2 = 1.0f - c * x2;
        float den = fmaxf(1.0f + 2.0f * c * xy + c * c * x2 * y2, 1e-15f);
        float P = Aa * s / den, Q = Bb2 / den;
        float g2 = P * P * S1t + 2.0f * P * Q * S3t + Q * Q * y2;
        float gn = fmaxf(sqrtf(g2), 1e-15f);
        if (gn > maxn) { float g = maxn / gn; P *= g; Q *= g; gn = maxn; }
        Pr[r] = P; Qr[r] = Q;
        Lr[r] = atanhf(fminf(sc * gn, 1.0f - 1e-7f)) / (gn * sc);
    }

    float q2[2] = {0.f, 0.f};
    #pragma unroll
    for (int nt = 0; nt < 8; nt++) {
        const int col = nhalf * 64 + nt * 8 + 2 * (l & 3);
        const float b0 = bv[col], b1 = bv[col + 1];
        float v0 = Lr[0] * (Pr[0] * acc[nt][0] + Qr[0] * b0);
        float v1 = Lr[0] * (Pr[0] * acc[nt][1] + Qr[0] * b1);
        float v2 = Lr[1] * (Pr[1] * acc[nt][2] + Qr[1] * b0);
        float v3 = Lr[1] * (Pr[1] * acc[nt][3] + Qr[1] * b1);
        v0 = (v0 >= 0.f) ? v0 : 0.01f * v0;
        v1 = (v1 >= 0.f) ? v1 : 0.01f * v1;
        v2 = (v2 >= 0.f) ? v2 : 0.01f * v2;
        v3 = (v3 >= 0.f) ? v3 : 0.01f * v3;
        acc[nt][0] = v0; acc[nt][1] = v1; acc[nt][2] = v2; acc[nt][3] = v3;
        q2[0] += v0*v0 + v1*v1;
        q2[1] += v2*v2 + v3*v3;
    }
    #pragma unroll
    for (int r = 0; r < 2; r++) {
        q2[r] += __shfl_xor_sync(0xffffffffu, q2[r], 1);
        q2[r] += __shfl_xor_sync(0xffffffffu, q2[r], 2);
    }
    if ((l & 3) == 0) {
        const int r0 = mb + (l >> 2);
        sredQ[r0][nhalf] = q2[0];
        sredQ[r0 + 8][nhalf] = q2[1];
    }
    __syncthreads();

    float er[2];
    const float sc2 = sqrtf(1.0f - c);
    const float mn2 = (1.0f - 4e-3f) / sc2;
    #pragma unroll
    for (int r = 0; r < 2; r++) {
        const int rl = mb + (l >> 2) + r * 8;
        float q2t = sredQ[rl][0] + sredQ[rl][1];
        float un = fmaxf(sqrtf(q2t), 1e-15f);
        float e  = tanhf(sc * un) / (sc * un);      // expmap0 with curvature c
        float vn = fmaxf(sqrtf(e * e * q2t), 1e-15f);
        if (vn > mn2) e *= mn2 / vn;                // proj with curvature 1-c
        er[r] = e;
    }

    const int g0 = rowbase + mb + (l >> 2);
    #pragma unroll
    for (int nt = 0; nt < 8; nt++) {
        const int col = nhalf * 64 + nt * 8 + 2 * (l & 3);
        *(float2*)&out[(size_t)g0 * DOUT + col] =
            make_float2(er[0] * acc[nt][0], er[0] * acc[nt][1]);
        *(float2*)&out[(size_t)(g0 + 8) * DOUT + col] =
            make_float2(er[1] * acc[nt][2], er[1] * acc[nt][3]);
    }
}

// ---------------- launch ----------------
extern "C" void kernel_launch(void* const* d_in, const int* in_sizes, int n_in,
                              void* d_out, int out_size)
{
    const float* x   = (const float*)d_in[0];
    const float* adj = (const float*)d_in[1];
    const float* cp  = (const float*)d_in[2];
    const float* lw  = (const float*)d_in[3];
    const float* lb  = (const float*)d_in[4];
    const float* aw  = (const float*)d_in[5];
    const float* ab  = (const float*)d_in[6];
    float* out = (float*)d_out;

    cudaFuncSetAttribute(k_lin_mma, cudaFuncAttributeMaxDynamicSharedMemorySize, DYN_SMEM);
    cudaFuncSetAttribute(k_agg_mma, cudaFuncAttributeMaxDynamicSharedMemorySize, DYN_SMEM);

    k_prep<<<2 * DOUT + 1, 128>>>(lw, lb, aw, ab, cp);
    k_lin_mma<<<NR / 64, 256, DYN_SMEM>>>(x, cp);
    k_sup_gemm<<<NR / 64, 128>>>(cp);
    k_agg_mma<<<NR / 64, 256, DYN_SMEM>>>(adj, ab, cp, out);
}

// round 14
// speedup vs baseline: 1.4928x; 1.4928x over previous
#include <cuda_runtime.h>
#include <cuda_bf16.h>
#include <cstdint>

// Problem dims (fixed for this problem instance)
#define NR   8192   // rows (nodes)
#define DIN  512    // input feature dim
#define DOUT 128    // output feature dim

// ---------------- scratch (static device globals; no allocation) ----------------
__device__ __align__(16) __nv_bfloat16 g_hw1b[DIN * DOUT]; // proj(expmap0(lin_weight))^T, bf16 [k][n]
__device__ __align__(16) float g_hw2[DOUT * DOUT];  // proj(expmap0(agg_weight))
__device__ __align__(16) float g_hb[DOUT];          // proj(expmap0(lin_bias))
__device__ float g_hb2s;                            // sum hb^2
__device__ float g_b2s;                             // sum agg_bias^2
__device__ __align__(16) float g_h[NR * DOUT];      // hyp_linear output
__device__ float g_hn[NR];                          // ||h_i|| (clamped)
__device__ __align__(16) __nv_bfloat16 g_supb[NR * DOUT];  // support, bf16, node-major

// ---------------- baseline-PTX helpers (no sm_103a-only instructions) ----------------
__device__ __forceinline__ uint32_t smem_u32(const void* p) {
    uint32_t a;
    asm("{ .reg .u64 t; cvta.to.shared.u64 t, %1; cvt.u32.u64 %0, t; }" : "=r"(a) : "l"(p));
    return a;
}
__device__ __forceinline__ uint32_t pack_bf16(float lo, float hi) {
    uint32_t r;
    asm("cvt.rn.bf16x2.f32 %0, %1, %2;" : "=r"(r) : "f"(hi), "f"(lo));
    return r;
}
__device__ __forceinline__ void cp_async16(uint32_t dst_smem, const void* src) {
    asm volatile("cp.async.cg.shared.global [%0], [%1], 16;" :: "r"(dst_smem), "l"(src) : "memory");
}
#define CP_COMMIT() asm volatile("cp.async.commit_group;" ::: "memory")
#define CP_WAIT0()  asm volatile("cp.async.wait_group 0;" ::: "memory")

#define LDSM_X4(r0, r1, r2, r3, addr) \
    asm volatile("ldmatrix.sync.aligned.m8n8.x4.shared.b16 {%0,%1,%2,%3}, [%4];" \
        : "=r"(r0), "=r"(r1), "=r"(r2), "=r"(r3) : "r"(addr))
#define LDSM_X4T(r0, r1, r2, r3, addr) \
    asm volatile("ldmatrix.sync.aligned.m8n8.x4.trans.shared.b16 {%0,%1,%2,%3}, [%4];" \
        : "=r"(r0), "=r"(r1), "=r"(r2), "=r"(r3) : "r"(addr))

// m16n8k16 bf16 MMA (compute_80 baseline feature)
__device__ __forceinline__ void mma_bf16(float* d,
                                         uint32_t a0, uint32_t a1, uint32_t a2, uint32_t a3,
                                         uint32_t b0, uint32_t b1) {
    asm volatile(
        "mma.sync.aligned.m16n8k16.row.col.f32.bf16.bf16.f32 "
        "{%0,%1,%2,%3}, {%4,%5,%6,%7}, {%8,%9}, {%0,%1,%2,%3};"
        : "+f"(d[0]), "+f"(d[1]), "+f"(d[2]), "+f"(d[3])
        : "r"(a0), "r"(a1), "r"(a2), "r"(a3), "r"(b0), "r"(b1));
}

// ---------------- helpers ----------------
__device__ __forceinline__ float blockReduceSum128(float v, float* sred) {
    #pragma unroll
    for (int o = 16; o > 0; o >>= 1) v += __shfl_xor_sync(0xffffffffu, v, o);
    int w = threadIdx.x >> 5;
    if ((threadIdx.x & 31) == 0) sred[w] = v;
    __syncthreads();
    float r = sred[0] + sred[1] + sred[2] + sred[3];
    __syncthreads();
    return r;
}

// ---------------- K0: weight prep: hw = proj(expmap0(W,c),c) ----------------
__global__ __launch_bounds__(128) void k_prep(
    const float* __restrict__ lw, const float* __restrict__ lb,
    const float* __restrict__ aw, const float* __restrict__ ab,
    const float* __restrict__ cp)
{
    __shared__ float sred[4];
    const float c    = cp[0];
    const float sc   = sqrtf(c);
    const float maxn = (1.0f - 4e-3f) / sc;
    const int b = blockIdx.x, t = threadIdx.x;

    if (b < DOUT) {                       // hw1 rows (len 512) -> bf16 transposed [k][n]
        const float* u = lw + b * DIN;
        float ss = 0.f;
        #pragma unroll
        for (int i = t; i < DIN; i += 128) { float v = u[i]; ss += v * v; }
        ss = blockReduceSum128(ss, sred);
        float un = fmaxf(sqrtf(ss), 1e-15f);
        float f  = tanhf(sc * un) / (sc * un);
        float vn = fmaxf(sqrtf(f * f * ss), 1e-15f);
        float coef = f * (vn > maxn ? maxn / vn : 1.0f);
        for (int i = t; i < DIN; i += 128)
            g_hw1b[(size_t)i * DOUT + b] = __float2bfloat16(coef * u[i]);
    } else if (b < 2 * DOUT) {            // hw2 rows (len 128)
        int r = b - DOUT;
        const float* u = aw + r * DOUT;
        float x = u[t];
        float ss = blockReduceSum128(x * x, sred);
        float un = fmaxf(sqrtf(ss), 1e-15f);
        float f  = tanhf(sc * un) / (sc * un);
        float vn = fmaxf(sqrtf(f * f * ss), 1e-15f);
        float coef = f * (vn > maxn ? maxn / vn : 1.0f);
        g_hw2[r * DOUT + t] = coef * x;
    } else {                              // hb + bias sumsq scalars
        float x = lb[t];
        float ss = blockReduceSum128(x * x, sred);
        float un = fmaxf(sqrtf(ss), 1e-15f);
        float f  = tanhf(sc * un) / (sc * un);
        float vn = fmaxf(sqrtf(f * f * ss), 1e-15f);
        float coef = f * (vn > maxn ? maxn / vn : 1.0f);
        g_hb[t] = coef * x;
        if (t == 0) g_hb2s = coef * coef * ss;
        float y = ab[t];
        float s2 = blockReduceSum128(y * y, sred);
        if (t == 0) g_b2s = s2;
    }
}

// ============ bf16-MMA tile constants (K1, K3: M=64 x N=128, KC=64) ============
// A smem [m=64][k=64] bf16, row stride 144 B -> ldmatrix conflict-free.
// B smem [k=64][n=128] bf16, row stride 272 B -> ldmatrix.trans conflict-free.
#define KC      64
#define ASTR_B  144
#define BSTR_B  272
#define A_BYTES (64 * ASTR_B)   // 9216
#define B_BYTES (KC * BSTR_B)   // 17408
#define DYN_SMEM (2 * (A_BYTES + B_BYTES))  // 53248

// ---------------- K1: h = hyp_linear(x,...) bf16 mma.sync ----------------
__global__ __launch_bounds__(256) void k_lin_mma(
    const float* __restrict__ x, const float* __restrict__ cp)
{
    extern __shared__ __align__(16) char dsm[];
    char* Ab0 = dsm;
    char* Bb0 = dsm + 2 * A_BYTES;
    __shared__ float bv[128];
    __shared__ float arow[64];
    __shared__ float sredS[64][2][3];

    const int t = threadIdx.x;
    const int w = t >> 5, l = t & 31;
    const int mb = (w & 3) * 16;
    const int nhalf = w >> 2;
    const int rowbase = blockIdx.x * 64;
    const float c  = cp[0];
    const float sc = sqrtf(c);

    if (t < 128) bv[t] = g_hb[t];

    const int arI = t >> 2, aq = t & 3;   // A loader: 4 threads/row, 16 floats each
    const float4* ap = (const float4*)(x + (size_t)(rowbase + arI) * DIN);
    const int bkr = t >> 2, bq = t & 3;   // B loader: 4 threads/k-row, 64 B each

    const uint32_t abase = smem_u32(Ab0);
    const uint32_t bbase = smem_u32(Bb0);

    float acc[8][4];
    #pragma unroll
    for (int i = 0; i < 8; i++)
        #pragma unroll
        for (int j = 0; j < 4; j++) acc[i][j] = 0.f;

    float asq = 0.f;
    float4 la[4];

    const int NCH = DIN / KC;  // 8

    // prologue: chunk 0
    #pragma unroll
    for (int i = 0; i < 4; i++) la[i] = ap[aq * 4 + i];
    #pragma unroll
    for (int i = 0; i < 2; i++) {
        float4 v0 = la[2 * i], v1 = la[2 * i + 1];
        asq += v0.x*v0.x + v0.y*v0.y + v0.z*v0.z + v0.w*v0.w
             + v1.x*v1.x + v1.y*v1.y + v1.z*v1.z + v1.w*v1.w;
        uint4 u = make_uint4(pack_bf16(v0.x, v0.y), pack_bf16(v0.z, v0.w),
                             pack_bf16(v1.x, v1.y), pack_bf16(v1.z, v1.w));
        *(uint4*)&Ab0[arI * ASTR_B + aq * 32 + i * 16] = u;
    }
    #pragma unroll
    for (int i = 0; i < 4; i++)
        cp_async16(bbase + (uint32_t)(bkr * BSTR_B + bq * 64 + i * 16),
                   (const char*)g_hw1b + ((size_t)bkr * DOUT + bq * 32 + i * 8) * 2);
    CP_COMMIT();
    CP_WAIT0();
    __syncthreads();

    for (int ck = 0; ck < NCH; ++ck) {
        const int cur = ck & 1, nxt = cur ^ 1;
        const bool more = (ck + 1 < NCH);
        if (more) {
            #pragma unroll
            for (int i = 0; i < 4; i++) la[i] = ap[(ck + 1) * 16 + aq * 4 + i];
            #pragma unroll
            for (int i = 0; i < 4; i++)
                cp_async16(bbase + (uint32_t)(nxt * B_BYTES + bkr * BSTR_B + bq * 64 + i * 16),
                           (const char*)g_hw1b + ((size_t)((ck + 1) * KC + bkr) * DOUT + bq * 32 + i * 8) * 2);
            CP_COMMIT();
        }
        {
            const uint32_t aT = abase + (uint32_t)cur * A_BYTES;
            const uint32_t bT = bbase + (uint32_t)cur * B_BYTES;
            #pragma unroll
            for (int ks = 0; ks < 4; ks++) {
                uint32_t a0, a1, a2, a3;
                uint32_t aaddr = aT + (uint32_t)((mb + (l & 15)) * ASTR_B + ks * 32 + (l >> 4) * 16);
                LDSM_X4(a0, a1, a2, a3, aaddr);
                #pragma unroll
                for (int p = 0; p < 4; p++) {
                    uint32_t b0, b1, b2, b3;
                    uint32_t baddr = bT + (uint32_t)((ks * 16 + (l & 15)) * BSTR_B
                                   + nhalf * 128 + (2 * p + (l >> 4)) * 16);
                    LDSM_X4T(b0, b1, b2, b3, baddr);
                    mma_bf16(acc[2 * p],     a0, a1, a2, a3, b0, b1);
                    mma_bf16(acc[2 * p + 1], a0, a1, a2, a3, b2, b3);
                }
            }
        }
        if (more) {
            #pragma unroll
            for (int i = 0; i < 2; i++) {
                float4 v0 = la[2 * i], v1 = la[2 * i + 1];
                asq += v0.x*v0.x + v0.y*v0.y + v0.z*v0.z + v0.w*v0.w
                     + v1.x*v1.x + v1.y*v1.y + v1.z*v1.z + v1.w*v1.w;
                uint4 u = make_uint4(pack_bf16(v0.x, v0.y), pack_bf16(v0.z, v0.w),
                                     pack_bf16(v1.x, v1.y), pack_bf16(v1.z, v1.w));
                *(uint4*)&Ab0[nxt * A_BYTES + arI * ASTR_B + aq * 32 + i * 16] = u;
            }
            CP_WAIT0();
        }
        __syncthreads();
    }

    // x row sumsq: combine 4 loader threads per row
    asq += __shfl_xor_sync(0xffffffffu, asq, 1);
    asq += __shfl_xor_sync(0xffffffffu, asq, 2);
    if ((t & 3) == 0) arow[arI] = asq;
    __syncthreads();

    // fragment-domain hyp_linear epilogue
    float S1[2] = {0.f, 0.f}, S2[2] = {0.f, 0.f}, S3[2] = {0.f, 0.f};
    #pragma unroll
    for (int nt = 0; nt < 8; nt++) {
        const int col = nhalf * 64 + nt * 8 + 2 * (l & 3);
        const float b0 = bv[col], b1 = bv[col + 1];
        float c0 = acc[nt][0], c1 = acc[nt][1], c2 = acc[nt][2], c3 = acc[nt][3];
        S1[0] += c0*c0 + c1*c1;  S2[0] += fabsf(c0) + fabsf(c1);  S3[0] += c0*b0 + c1*b1;
        S1[1] += c2*c2 + c3*c3;  S2[1] += fabsf(c2) + fabsf(c3);  S3[1] += c2*b0 + c3*b1;
    }
    #pragma unroll
    for (int r = 0; r < 2; r++) {
        S1[r] += __shfl_xor_sync(0xffffffffu, S1[r], 1);
        S1[r] += __shfl_xor_sync(0xffffffffu, S1[r], 2);
        S2[r] += __shfl_xor_sync(0xffffffffu, S2[r], 1);
        S2[r] += __shfl_xor_sync(0xffffffffu, S2[r], 2);
        S3[r] += __shfl_xor_sync(0xffffffffu, S3[r], 1);
        S3[r] += __shfl_xor_sync(0xffffffffu, S3[r], 2);
    }
    if ((l & 3) == 0) {
        const int r0 = mb + (l >> 2);
        sredS[r0][nhalf][0] = S1[0]; sredS[r0][nhalf][1] = S2[0]; sredS[r0][nhalf][2] = S3[0];
        sredS[r0 + 8][nhalf][0] = S1[1]; sredS[r0 + 8][nhalf][1] = S2[1]; sredS[r0 + 8][nhalf][2] = S3[1];
    }
    __syncthreads();

    float Pr[2], Qr[2];
    const float y2 = g_hb2s;
    const float maxn = (1.0f - 4e-3f) / sc;
    #pragma unroll
    for (int r = 0; r < 2; r++) {
        const int rl = mb + (l >> 2) + r * 8;
        float S1t = sredS[rl][0][0] + sredS[rl][1][0];
        float S2t = sredS[rl][0][1] + sredS[rl][1][1];
        float S3t = sredS[rl][0][2] + sredS[rl][1][2];
        float xn  = fmaxf(sqrtf(arow[rl]), 1e-15f);
        float mxn = fmaxf(sqrtf(S1t), 1e-15f);
        float at  = atanhf(fminf(sc * xn, 1.0f - 1e-7f));
        float s   = tanhf(mxn / xn * at) / (mxn * sc);
        if (S2t == 0.f) s = 0.f;
        float rn = fmaxf(sqrtf(s * s * S1t), 1e-15f);
        if (rn > maxn) s *= maxn / rn;          // proj before mobius_add
        float x2 = s * s * S1t;
        float xy = s * S3t;
        float Aa = 1.0f + 2.0f * c * xy + c * y2;
        float Bb2 = 1.0f - c * x2;
        float den = fmaxf(1.0f + 2.0f * c * xy + c * c * x2 * y2, 1e-15f);
        float P = Aa * s / den, Q = Bb2 / den;
        float h2 = P * P * S1t + 2.0f * P * Q * S3t + Q * Q * y2;
        float hn = fmaxf(sqrtf(h2), 1e-15f);
        if (hn > maxn) { float g = maxn / hn; P *= g; Q *= g; hn = maxn; }
        Pr[r] = P; Qr[r] = Q;
        if (((l & 3) == 0) && nhalf == 0) g_hn[rowbase + rl] = hn;
    }

    const int g0 = rowbase + mb + (l >> 2);
    #pragma unroll
    for (int nt = 0; nt < 8; nt++) {
        const int col = nhalf * 64 + nt * 8 + 2 * (l & 3);
        *(float2*)&g_h[(size_t)g0 * DOUT + col] =
            make_float2(Pr[0] * acc[nt][0] + Qr[0] * bv[col],
                        Pr[0] * acc[nt][1] + Qr[0] * bv[col + 1]);
        *(float2*)&g_h[(size_t)(g0 + 8) * DOUT + col] =
            make_float2(Pr[1] * acc[nt][2] + Qr[1] * bv[col],
                        Pr[1] * acc[nt][3] + Qr[1] * bv[col + 1]);
    }
}

// ============ FFMA GEMM tile config (K2) ============
#define BK  32
#define BMP 68
#define BN  128

// ---------------- K2: support = mobius_matvec(hw2, h) fused GEMM -> bf16 ----------------
__global__ __launch_bounds__(128) void k_sup_gemm(const float* __restrict__ cp) {
    __shared__ __align__(16) float pool[BK * BMP + BK * BN];
    __shared__ float par[64];
    float* As = pool;
    float* Bs = pool + BK * BMP;

    const int t = threadIdx.x;
    const int rowbase = blockIdx.x * 64;
    const float c  = cp[0];
    const float sc = sqrtf(c);

    const int tr = t >> 4, tc = t & 15;
    const int ar = t >> 3, ac = (t & 7) * 4;

    float acc[8][8];
    #pragma unroll
    for (int i = 0; i < 8; i++)
        #pragma unroll
        for (int j = 0; j < 8; j++) acc[i][j] = 0.f;

    float4 la[4], lb8[8];
    #pragma unroll
    for (int p = 0; p < 4; p++)
        la[p] = *(const float4*)&g_h[(size_t)(rowbase + p * 16 + ar) * DOUT + ac];
    #pragma unroll
    for (int f = 0; f < 8; f++)
        lb8[f] = *(const float4*)&g_hw2[t * DOUT + f * 4];

    const int ITERS = DOUT / BK;  // 4
    for (int it = 0; it < ITERS; ++it) {
        __syncthreads();
        #pragma unroll
        for (int p = 0; p < 4; p++) {
            float4 v = la[p]; int r = p * 16 + ar;
            As[(ac + 0) * BMP + r] = v.x; As[(ac + 1) * BMP + r] = v.y;
            As[(ac + 2) * BMP + r] = v.z; As[(ac + 3) * BMP + r] = v.w;
        }
        #pragma unroll
        for (int f = 0; f < 8; f++) {
            float4 v = lb8[f];
            Bs[(f * 4 + 0) * BN + t] = v.x; Bs[(f * 4 + 1) * BN + t] = v.y;
            Bs[(f * 4 + 2) * BN + t] = v.z; Bs[(f * 4 + 3) * BN + t] = v.w;
        }
        __syncthreads();
        if (it + 1 < ITERS) {
            int kt = (it + 1) * BK;
            #pragma unroll
            for (int p = 0; p < 4; p++)
                la[p] = *(const float4*)&g_h[(size_t)(rowbase + p * 16 + ar) * DOUT + kt + ac];
            #pragma unroll
            for (int f = 0; f < 8; f++)
                lb8[f] = *(const float4*)&g_hw2[t * DOUT + kt + f * 4];
        }
        #pragma unroll
        for (int kk = 0; kk < BK; kk++) {
            float4 a0 = *(const float4*)&As[kk * BMP + tr * 8];
            float4 a1 = *(const float4*)&As[kk * BMP + tr * 8 + 4];
            float4 b0 = *(const float4*)&Bs[kk * BN + tc * 4];
            float4 b1 = *(const float4*)&Bs[kk * BN + tc * 4 + 64];
            float av[8] = {a0.x,a0.y,a0.z,a0.w,a1.x,a1.y,a1.z,a1.w};
            float bv[8] = {b0.x,b0.y,b0.z,b0.w,b1.x,b1.y,b1.z,b1.w};
            #pragma unroll
            for (int i = 0; i < 8; i++)
                #pragma unroll
                for (int j = 0; j < 8; j++) acc[i][j] += av[i] * bv[j];
        }
    }
    __syncthreads();

    float* red = pool;  // [64][16][2]
    #pragma unroll
    for (int i = 0; i < 8; i++) {
        int r = tr * 8 + i;
        float p1 = 0.f, p2 = 0.f;
        #pragma unroll
        for (int j = 0; j < 8; j++) { float v = acc[i][j]; p1 += v * v; p2 += fabsf(v); }
        red[(r * 16 + tc) * 2 + 0] = p1;
        red[(r * 16 + tc) * 2 + 1] = p2;
    }
    __syncthreads();
    if (t < 64) {
        float S1 = 0.f, S2 = 0.f;
        #pragma unroll
        for (int q = 0; q < 16; q++) {
            S1 += red[(t * 16 + q) * 2 + 0];
            S2 += red[(t * 16 + q) * 2 + 1];
        }
        float hn  = g_hn[rowbase + t];
        float mxn = fmaxf(sqrtf(S1), 1e-15f);
        float at  = atanhf(fminf(sc * hn, 1.0f - 1e-7f));
        float s   = tanhf(mxn / hn * at) / (mxn * sc);
        if (S2 == 0.f) s = 0.f;
        par[t] = s;
    }
    __syncthreads();
    #pragma unroll
    for (int i = 0; i < 8; i++) {
        int r = tr * 8 + i;
        float s = par[r];
        uint32_t u0 = pack_bf16(s * acc[i][0], s * acc[i][1]);
        uint32_t u1 = pack_bf16(s * acc[i][2], s * acc[i][3]);
        uint32_t u2 = pack_bf16(s * acc[i][4], s * acc[i][5]);
        uint32_t u3 = pack_bf16(s * acc[i][6], s * acc[i][7]);
        *(uint2*)&g_supb[(size_t)(rowbase + r) * DOUT + tc * 4]      = make_uint2(u0, u1);
        *(uint2*)&g_supb[(size_t)(rowbase + r) * DOUT + 64 + tc * 4] = make_uint2(u2, u3);
    }
}

// ---------------- K3: bf16 mma.sync adj@sup + fused hyperbolic epilogue ----------------
// 128 CTAs x 512 threads (16 warps, 4/SMSP). CTA: M=64 x N=128, K=8192 chunked by KC=64.
// Warp w: m-band (w&3)*16, n-quarter (w>>2)*32. Same tile as R11 but 2x warps for issue hiding.
__global__ __launch_bounds__(512) void k_agg_mma(
    const float* __restrict__ adj, const float* __restrict__ bias,
    const float* __restrict__ cp, float* __restrict__ out)
{
    extern __shared__ __align__(16) char dsm[];
    char* Ab0 = dsm;
    char* Bb0 = dsm + 2 * A_BYTES;
    __shared__ float bv[128];
    __shared__ float arow[64];
    __shared__ float sredS[64][4][3];
    __shared__ float sredQ[64][4];

    const int t = threadIdx.x;
    const int w = t >> 5, l = t & 31;
    const int mb = (w & 3) * 16;      // warp m-band (0..3)*16
    const int nq = w >> 2;            // warp n-quarter (0..3)
    const int rowbase = blockIdx.x * 64;
    const float c  = cp[0];
    const float sc = sqrtf(c);

    if (t < 128) bv[t] = bias[t];

    // A loader: 8 threads/row, 8 floats (2 float4) each
    const int arI = t >> 3, aq = t & 7;
    const float4* ap = (const float4*)(adj + (size_t)(rowbase + arI) * NR);
    // B loader: 8 threads/k-row, 32 B (2 cp.async16) each
    const int bkr = t >> 3, bq = t & 7;

    const uint32_t abase = smem_u32(Ab0);
    const uint32_t bbase = smem_u32(Bb0);

    float acc[4][4];
    #pragma unroll
    for (int i = 0; i < 4; i++)
        #pragma unroll
        for (int j = 0; j < 4; j++) acc[i][j] = 0.f;

    float asq = 0.f;
    float4 la0, la1;

    const int NCH = NR / KC;  // 128

    // prologue: chunk 0
    la0 = ap[aq * 2]; la1 = ap[aq * 2 + 1];
    asq += la0.x*la0.x + la0.y*la0.y + la0.z*la0.z + la0.w*la0.w
         + la1.x*la1.x + la1.y*la1.y + la1.z*la1.z + la1.w*la1.w;
    {
        uint4 u = make_uint4(pack_bf16(la0.x, la0.y), pack_bf16(la0.z, la0.w),
                             pack_bf16(la1.x, la1.y), pack_bf16(la1.z, la1.w));
        *(uint4*)&Ab0[arI * ASTR_B + aq * 16] = u;
    }
    #pragma unroll
    for (int i = 0; i < 2; i++)
        cp_async16(bbase + (uint32_t)(bkr * BSTR_B + bq * 32 + i * 16),
                   (const char*)g_supb + ((size_t)bkr * DOUT + bq * 16 + i * 8) * 2);
    CP_COMMIT();
    CP_WAIT0();
    __syncthreads();

    for (int ck = 0; ck < NCH; ++ck) {
        const int cur = ck & 1, nxt = cur ^ 1;
        const bool more = (ck + 1 < NCH);
        if (more) {
            la0 = ap[(ck + 1) * 16 + aq * 2];
            la1 = ap[(ck + 1) * 16 + aq * 2 + 1];
            #pragma unroll
            for (int i = 0; i < 2; i++)
                cp_async16(bbase + (uint32_t)(nxt * B_BYTES + bkr * BSTR_B + bq * 32 + i * 16),
                           (const char*)g_supb + ((size_t)((ck + 1) * KC + bkr) * DOUT + bq * 16 + i * 8) * 2);
            CP_COMMIT();
        }
        {
            const uint32_t aT = abase + (uint32_t)cur * A_BYTES;
            const uint32_t bT = bbase + (uint32_t)cur * B_BYTES;
            #pragma unroll
            for (int ks = 0; ks < 4; ks++) {
                uint32_t a0, a1, a2, a3;
                uint32_t aaddr = aT + (uint32_t)((mb + (l & 15)) * ASTR_B + ks * 32 + (l >> 4) * 16);
                LDSM_X4(a0, a1, a2, a3, aaddr);
                #pragma unroll
                for (int p = 0; p < 2; p++) {
                    uint32_t b0, b1, b2, b3;
                    uint32_t baddr = bT + (uint32_t)((ks * 16 + (l & 15)) * BSTR_B
                                   + nq * 64 + (2 * p + (l >> 4)) * 16);
                    LDSM_X4T(b0, b1, b2, b3, baddr);
                    mma_bf16(acc[2 * p],     a0, a1, a2, a3, b0, b1);
                    mma_bf16(acc[2 * p + 1], a0, a1, a2, a3, b2, b3);
                }
            }
        }
        if (more) {
            asq += la0.x*la0.x + la0.y*la0.y + la0.z*la0.z + la0.w*la0.w
                 + la1.x*la1.x + la1.y*la1.y + la1.z*la1.z + la1.w*la1.w;
            uint4 u = make_uint4(pack_bf16(la0.x, la0.y), pack_bf16(la0.z, la0.w),
                                 pack_bf16(la1.x, la1.y), pack_bf16(la1.z, la1.w));
            *(uint4*)&Ab0[nxt * A_BYTES + arI * ASTR_B + aq * 16] = u;
            CP_WAIT0();
        }
        __syncthreads();
    }

    // adj row sumsq: combine 8 loader threads per row
    asq += __shfl_xor_sync(0xffffffffu, asq, 1);
    asq += __shfl_xor_sync(0xffffffffu, asq, 2);
    asq += __shfl_xor_sync(0xffffffffu, asq, 4);
    if ((t & 7) == 0) arow[arI] = asq;
    __syncthreads();

    // fragment-domain hyperbolic epilogue (N split across 4 warp-quarters)
    // lane rows: r0 = mb + (l>>2), r1 = r0 + 8; cols: nq*32 + nt*8 + 2*(l&3)+{0,1}
    float S1[2] = {0.f, 0.f}, S2[2] = {0.f, 0.f}, S3[2] = {0.f, 0.f};
    #pragma unroll
    for (int nt = 0; nt < 4; nt++) {
        const int col = nq * 32 + nt * 8 + 2 * (l & 3);
        const float b0 = bv[col], b1 = bv[col + 1];
        float c0 = acc[nt][0], c1 = acc[nt][1], c2 = acc[nt][2], c3 = acc[nt][3];
        S1[0] += c0*c0 + c1*c1;  S2[0] += fabsf(c0) + fabsf(c1);  S3[0] += c0*b0 + c1*b1;
        S1[1] += c2*c2 + c3*c3;  S2[1] += fabsf(c2) + fabsf(c3);  S3[1] += c2*b0 + c3*b1;
    }
    #pragma unroll
    for (int r = 0; r < 2; r++) {
        S1[r] += __shfl_xor_sync(0xffffffffu, S1[r], 1);
        S1[r] += __shfl_xor_sync(0xffffffffu, S1[r], 2);
        S2[r] += __shfl_xor_sync(0xffffffffu, S2[r], 1);
        S2[r] += __shfl_xor_sync(0xffffffffu, S2[r], 2);
        S3[r] += __shfl_xor_sync(0xffffffffu, S3[r], 1);
        S3[r] += __shfl_xor_sync(0xffffffffu, S3[r], 2);
    }
    if ((l & 3) == 0) {
        const int r0 = mb + (l >> 2);
        sredS[r0][nq][0] = S1[0]; sredS[r0][nq][1] = S2[0]; sredS[r0][nq][2] = S3[0];
        sredS[r0 + 8][nq][0] = S1[1]; sredS[r0 + 8][nq][1] = S2[1]; sredS[r0 + 8][nq][2] = S3[1];
    }
    __syncthreads();

    float Pr[2], Qr[2], Lr[2];
    const float y2 = g_b2s;
    const float maxn = (1.0f - 4e-3f) / sc;
    #pragma unroll
    for (int r = 0; r < 2; r++) {
        const int rl = mb + (l >> 2) + r * 8;
        float S1t = sredS[rl][0][0] + sredS[rl][1][0] + sredS[rl][2][0] + sredS[rl][3][0];
        float S2t = sredS[rl][0][1] + sredS[rl][1][1] + sredS[rl][2][1] + sredS[rl][3][1];
        float S3t = sredS[rl][0][2] + sredS[rl][1][2] + sredS[rl][2][2] + sredS[rl][3][2];
        float an  = fmaxf(sqrtf(arow[rl]), 1e-15f);
        float mxn = fmaxf(sqrtf(S1t), 1e-15f);
        float at  = atanhf(fminf(sc * an, 1.0f - 1e-7f));
        float s   = tanhf(mxn / an * at) / (mxn * sc);
        if (S2t == 0.f) s = 0.f;
        float x2 = s * s * S1t;
        float xy = s * S3t;
        float Aa = 1.0f + 2.0f * c * xy + c * y2;
        float Bb2 = 1.0f - c * x2;
        float den = fmaxf(1.0f + 2.0f * c * xy + c * c * x2 * y2, 1e-15f);
        float P = Aa * s / den, Q = Bb2 / den;
        float g2 = P * P * S1t + 2.0f * P * Q * S3t + Q * Q * y2;
        float gn = fmaxf(sqrtf(g2), 1e-15f);
        if (gn > maxn) { float g = maxn / gn; P *= g; Q *= g; gn = maxn; }
        Pr[r] = P; Qr[r] = Q;
        Lr[r] = atanhf(fminf(sc * gn, 1.0f - 1e-7f)) / (gn * sc);
    }

    float q2[2] = {0.f, 0.f};
    #pragma unroll
    for (int nt = 0; nt < 4; nt++) {
        const int col = nq * 32 + nt * 8 + 2 * (l & 3);
        const float b0 = bv[col], b1 = bv[col + 1];
        float v0 = Lr[0] * (Pr[0] * acc[nt][0] + Qr[0] * b0);
        float v1 = Lr[0] * (Pr[0] * acc[nt][1] + Qr[0] * b1);
        float v2 = Lr[1] * (Pr[1] * acc[nt][2] + Qr[1] * b0);
        float v3 = Lr[1] * (Pr[1] * acc[nt][3] + Qr[1] * b1);
        v0 = (v0 >= 0.f) ? v0 : 0.01f * v0;
        v1 = (v1 >= 0.f) ? v1 : 0.01f * v1;
        v2 = (v2 >= 0.f) ? v2 : 0.01f * v2;
        v3 = (v3 >= 0.f) ? v3 : 0.01f * v3;
        acc[nt][0] = v0; acc[nt][1] = v1; acc[nt][2] = v2; acc[nt][3] = v3;
        q2[0] += v0*v0 + v1*v1;
        q2[1] += v2*v2 + v3*v3;
    }
    #pragma unroll
    for (int r = 0; r < 2; r++) {
        q2[r] += __shfl_xor_sync(0xffffffffu, q2[r], 1);
        q2[r] += __shfl_xor_sync(0xffffffffu, q2[r], 2);
    }
    if ((l & 3) == 0) {
        const int r0 = mb + (l >> 2);
        sredQ[r0][nq] = q2[0];
        sredQ[r0 + 8][nq] = q2[1];
    }
    __syncthreads();

    float er[2];
    const float sc2 = sqrtf(1.0f - c);
    const float mn2 = (1.0f - 4e-3f) / sc2;
    #pragma unroll
    for (int r = 0; r < 2; r++) {
        const int rl = mb + (l >> 2) + r * 8;
        float q2t = sredQ[rl][0] + sredQ[rl][1] + sredQ[rl][2] + sredQ[rl][3];
        float un = fmaxf(sqrtf(q2t), 1e-15f);
        float e  = tanhf(sc * un) / (sc * un);      // expmap0 with curvature c
        float vn = fmaxf(sqrtf(e * e * q2t), 1e-15f);
        if (vn > mn2) e *= mn2 / vn;                // proj with curvature 1-c
        er[r] = e;
    }

    const int g0 = rowbase + mb + (l >> 2);
    #pragma unroll
    for (int nt = 0; nt < 4; nt++) {
        const int col = nq * 32 + nt * 8 + 2 * (l & 3);
        *(float2*)&out[(size_t)g0 * DOUT + col] =
            make_float2(er[0] * acc[nt][0], er[0] * acc[nt][1]);
        *(float2*)&out[(size_t)(g0 + 8) * DOUT + col] =
            make_float2(er[1] * acc[nt][2], er[1] * acc[nt][3]);
    }
}

// ---------------- launch ----------------
extern "C" void kernel_launch(void* const* d_in, const int* in_sizes, int n_in,
                              void* d_out, int out_size)
{
    const float* x   = (const float*)d_in[0];
    const float* adj = (const float*)d_in[1];
    const float* cp  = (const float*)d_in[2];
    const float* lw  = (const float*)d_in[3];
    const float* lb  = (const float*)d_in[4];
    const float* aw  = (const float*)d_in[5];
    const float* ab  = (const float*)d_in[6];
    float* out = (float*)d_out;

    cudaFuncSetAttribute(k_lin_mma, cudaFuncAttributeMaxDynamicSharedMemorySize, DYN_SMEM);
    cudaFuncSetAttribute(k_agg_mma, cudaFuncAttributeMaxDynamicSharedMemorySize, DYN_SMEM);

    k_prep<<<2 * DOUT + 1, 128>>>(lw, lb, aw, ab, cp);
    k_lin_mma<<<NR / 64, 256, DYN_SMEM>>>(x, cp);
    k_sup_gemm<<<NR / 64, 128>>>(cp);
    k_agg_mma<<<NR / 64, 512, DYN_SMEM>>>(adj, ab, cp, out);
}

// round 16
// speedup vs baseline: 1.5629x; 1.0469x over previous
#include <cuda_runtime.h>
#include <cuda_bf16.h>
#include <cstdint>

// Problem dims (fixed for this problem instance)
#define NR   8192   // rows (nodes)
#define DIN  512    // input feature dim
#define DOUT 128    // output feature dim

// ---------------- scratch (static device globals; no allocation) ----------------
__device__ __align__(16) __nv_bfloat16 g_hw1b[DIN * DOUT]; // proj(expmap0(lin_weight))^T, bf16 [k][n]
__device__ __align__(16) float g_hw2[DOUT * DOUT];  // proj(expmap0(agg_weight))
__device__ __align__(16) float g_hb[DOUT];          // proj(expmap0(lin_bias))
__device__ float g_hb2s;                            // sum hb^2
__device__ float g_b2s;                             // sum agg_bias^2
__device__ __align__(16) float g_h[NR * DOUT];      // hyp_linear output
__device__ float g_hn[NR];                          // ||h_i|| (clamped)
__device__ __align__(16) __nv_bfloat16 g_supb[NR * DOUT];  // support, bf16, node-major

// ---------------- baseline-PTX helpers (no sm_103a-only instructions) ----------------
__device__ __forceinline__ uint32_t smem_u32(const void* p) {
    uint32_t a;
    asm("{ .reg .u64 t; cvta.to.shared.u64 t, %1; cvt.u32.u64 %0, t; }" : "=r"(a) : "l"(p));
    return a;
}
__device__ __forceinline__ uint32_t pack_bf16(float lo, float hi) {
    uint32_t r;
    asm("cvt.rn.bf16x2.f32 %0, %1, %2;" : "=r"(r) : "f"(hi), "f"(lo));
    return r;
}
__device__ __forceinline__ void cp_async16(uint32_t dst_smem, const void* src) {
    asm volatile("cp.async.cg.shared.global [%0], [%1], 16;" :: "r"(dst_smem), "l"(src) : "memory");
}
#define CP_COMMIT() asm volatile("cp.async.commit_group;" ::: "memory")
#define CP_WAIT0()  asm volatile("cp.async.wait_group 0;" ::: "memory")
#define CP_WAIT2()  asm volatile("cp.async.wait_group 2;" ::: "memory")

#define LDSM_X4(r0, r1, r2, r3, addr) \
    asm volatile("ldmatrix.sync.aligned.m8n8.x4.shared.b16 {%0,%1,%2,%3}, [%4];" \
        : "=r"(r0), "=r"(r1), "=r"(r2), "=r"(r3) : "r"(addr))
#define LDSM_X4T(r0, r1, r2, r3, addr) \
    asm volatile("ldmatrix.sync.aligned.m8n8.x4.trans.shared.b16 {%0,%1,%2,%3}, [%4];" \
        : "=r"(r0), "=r"(r1), "=r"(r2), "=r"(r3) : "r"(addr))

// m16n8k16 bf16 MMA (compute_80 baseline feature)
__device__ __forceinline__ void mma_bf16(float* d,
                                         uint32_t a0, uint32_t a1, uint32_t a2, uint32_t a3,
                                         uint32_t b0, uint32_t b1) {
    asm volatile(
        "mma.sync.aligned.m16n8k16.row.col.f32.bf16.bf16.f32 "
        "{%0,%1,%2,%3}, {%4,%5,%6,%7}, {%8,%9}, {%0,%1,%2,%3};"
        : "+f"(d[0]), "+f"(d[1]), "+f"(d[2]), "+f"(d[3])
        : "r"(a0), "r"(a1), "r"(a2), "r"(a3), "r"(b0), "r"(b1));
}

// ---------------- helpers ----------------
__device__ __forceinline__ float blockReduceSum128(float v, float* sred) {
    #pragma unroll
    for (int o = 16; o > 0; o >>= 1) v += __shfl_xor_sync(0xffffffffu, v, o);
    int w = threadIdx.x >> 5;
    if ((threadIdx.x & 31) == 0) sred[w] = v;
    __syncthreads();
    float r = sred[0] + sred[1] + sred[2] + sred[3];
    __syncthreads();
    return r;
}

// ---------------- K0: weight prep: hw = proj(expmap0(W,c),c) ----------------
__global__ __launch_bounds__(128) void k_prep(
    const float* __restrict__ lw, const float* __restrict__ lb,
    const float* __restrict__ aw, const float* __restrict__ ab,
    const float* __restrict__ cp)
{
    __shared__ float sred[4];
    const float c    = cp[0];
    const float sc   = sqrtf(c);
    const float maxn = (1.0f - 4e-3f) / sc;
    const int b = blockIdx.x, t = threadIdx.x;

    if (b < DOUT) {                       // hw1 rows (len 512) -> bf16 transposed [k][n]
        const float* u = lw + b * DIN;
        float ss = 0.f;
        #pragma unroll
        for (int i = t; i < DIN; i += 128) { float v = u[i]; ss += v * v; }
        ss = blockReduceSum128(ss, sred);
        float un = fmaxf(sqrtf(ss), 1e-15f);
        float f  = tanhf(sc * un) / (sc * un);
        float vn = fmaxf(sqrtf(f * f * ss), 1e-15f);
        float coef = f * (vn > maxn ? maxn / vn : 1.0f);
        for (int i = t; i < DIN; i += 128)
            g_hw1b[(size_t)i * DOUT + b] = __float2bfloat16(coef * u[i]);
    } else if (b < 2 * DOUT) {            // hw2 rows (len 128)
        int r = b - DOUT;
        const float* u = aw + r * DOUT;
        float x = u[t];
        float ss = blockReduceSum128(x * x, sred);
        float un = fmaxf(sqrtf(ss), 1e-15f);
        float f  = tanhf(sc * un) / (sc * un);
        float vn = fmaxf(sqrtf(f * f * ss), 1e-15f);
        float coef = f * (vn > maxn ? maxn / vn : 1.0f);
        g_hw2[r * DOUT + t] = coef * x;
    } else {                              // hb + bias sumsq scalars
        float x = lb[t];
        float ss = blockReduceSum128(x * x, sred);
        float un = fmaxf(sqrtf(ss), 1e-15f);
        float f  = tanhf(sc * un) / (sc * un);
        float vn = fmaxf(sqrtf(f * f * ss), 1e-15f);
        float coef = f * (vn > maxn ? maxn / vn : 1.0f);
        g_hb[t] = coef * x;
        if (t == 0) g_hb2s = coef * coef * ss;
        float y = ab[t];
        float s2 = blockReduceSum128(y * y, sred);
        if (t == 0) g_b2s = s2;
    }
}

// ============ bf16-MMA tile constants ============
#define KC      64
#define ASTR_B  144
#define BSTR_B  272
#define A_BYTES (64 * ASTR_B)   // 9216
#define B_BYTES (KC * BSTR_B)   // 17408
#define DYN_SMEM (2 * (A_BYTES + B_BYTES))  // 53248  (K1)
// K3: 3-stage fp32 A ring + single bf16 A buf + 2-stage B
#define A32_BYTES (64 * KC * 4)             // 16384 per fp32 stage
#define DYN3_SMEM (3 * A32_BYTES + A_BYTES + 2 * B_BYTES)  // 93184

// ---------------- K1: h = hyp_linear(x,...) bf16 mma.sync ----------------
__global__ __launch_bounds__(256) void k_lin_mma(
    const float* __restrict__ x, const float* __restrict__ cp)
{
    extern __shared__ __align__(16) char dsm[];
    char* Ab0 = dsm;
    char* Bb0 = dsm + 2 * A_BYTES;
    __shared__ float bv[128];
    __shared__ float arow[64];
    __shared__ float sredS[64][2][3];

    const int t = threadIdx.x;
    const int w = t >> 5, l = t & 31;
    const int mb = (w & 3) * 16;
    const int nhalf = w >> 2;
    const int rowbase = blockIdx.x * 64;
    const float c  = cp[0];
    const float sc = sqrtf(c);

    if (t < 128) bv[t] = g_hb[t];

    const int arI = t >> 2, aq = t & 3;   // A loader: 4 threads/row, 16 floats each
    const float4* ap = (const float4*)(x + (size_t)(rowbase + arI) * DIN);
    const int bkr = t >> 2, bq = t & 3;   // B loader: 4 threads/k-row, 64 B each

    const uint32_t abase = smem_u32(Ab0);
    const uint32_t bbase = smem_u32(Bb0);

    float acc[8][4];
    #pragma unroll
    for (int i = 0; i < 8; i++)
        #pragma unroll
        for (int j = 0; j < 4; j++) acc[i][j] = 0.f;

    float asq = 0.f;
    float4 la[4];

    const int NCH = DIN / KC;  // 8

    // prologue: chunk 0
    #pragma unroll
    for (int i = 0; i < 4; i++) la[i] = ap[aq * 4 + i];
    #pragma unroll
    for (int i = 0; i < 2; i++) {
        float4 v0 = la[2 * i], v1 = la[2 * i + 1];
        asq += v0.x*v0.x + v0.y*v0.y + v0.z*v0.z + v0.w*v0.w
             + v1.x*v1.x + v1.y*v1.y + v1.z*v1.z + v1.w*v1.w;
        uint4 u = make_uint4(pack_bf16(v0.x, v0.y), pack_bf16(v0.z, v0.w),
                             pack_bf16(v1.x, v1.y), pack_bf16(v1.z, v1.w));
        *(uint4*)&Ab0[arI * ASTR_B + aq * 32 + i * 16] = u;
    }
    #pragma unroll
    for (int i = 0; i < 4; i++)
        cp_async16(bbase + (uint32_t)(bkr * BSTR_B + bq * 64 + i * 16),
                   (const char*)g_hw1b + ((size_t)bkr * DOUT + bq * 32 + i * 8) * 2);
    CP_COMMIT();
    CP_WAIT0();
    __syncthreads();

    for (int ck = 0; ck < NCH; ++ck) {
        const int cur = ck & 1, nxt = cur ^ 1;
        const bool more = (ck + 1 < NCH);
        if (more) {
            #pragma unroll
            for (int i = 0; i < 4; i++) la[i] = ap[(ck + 1) * 16 + aq * 4 + i];
            #pragma unroll
            for (int i = 0; i < 4; i++)
                cp_async16(bbase + (uint32_t)(nxt * B_BYTES + bkr * BSTR_B + bq * 64 + i * 16),
                           (const char*)g_hw1b + ((size_t)((ck + 1) * KC + bkr) * DOUT + bq * 32 + i * 8) * 2);
            CP_COMMIT();
        }
        {
            const uint32_t aT = abase + (uint32_t)cur * A_BYTES;
            const uint32_t bT = bbase + (uint32_t)cur * B_BYTES;
            #pragma unroll
            for (int ks = 0; ks < 4; ks++) {
                uint32_t a0, a1, a2, a3;
                uint32_t aaddr = aT + (uint32_t)((mb + (l & 15)) * ASTR_B + ks * 32 + (l >> 4) * 16);
                LDSM_X4(a0, a1, a2, a3, aaddr);
                #pragma unroll
                for (int p = 0; p < 4; p++) {
                    uint32_t b0, b1, b2, b3;
                    uint32_t baddr = bT + (uint32_t)((ks * 16 + (l & 15)) * BSTR_B
                                   + nhalf * 128 + (2 * p + (l >> 4)) * 16);
                    LDSM_X4T(b0, b1, b2, b3, baddr);
                    mma_bf16(acc[2 * p],     a0, a1, a2, a3, b0, b1);
                    mma_bf16(acc[2 * p + 1], a0, a1, a2, a3, b2, b3);
                }
            }
        }
        if (more) {
            #pragma unroll
            for (int i = 0; i < 2; i++) {
                float4 v0 = la[2 * i], v1 = la[2 * i + 1];
                asq += v0.x*v0.x + v0.y*v0.y + v0.z*v0.z + v0.w*v0.w
                     + v1.x*v1.x + v1.y*v1.y + v1.z*v1.z + v1.w*v1.w;
                uint4 u = make_uint4(pack_bf16(v0.x, v0.y), pack_bf16(v0.z, v0.w),
                                     pack_bf16(v1.x, v1.y), pack_bf16(v1.z, v1.w));
                *(uint4*)&Ab0[nxt * A_BYTES + arI * ASTR_B + aq * 32 + i * 16] = u;
            }
            CP_WAIT0();
        }
        __syncthreads();
    }

    // x row sumsq: combine 4 loader threads per row
    asq += __shfl_xor_sync(0xffffffffu, asq, 1);
    asq += __shfl_xor_sync(0xffffffffu, asq, 2);
    if ((t & 3) == 0) arow[arI] = asq;
    __syncthreads();

    // fragment-domain hyp_linear epilogue
    float S1[2] = {0.f, 0.f}, S2[2] = {0.f, 0.f}, S3[2] = {0.f, 0.f};
    #pragma unroll
    for (int nt = 0; nt < 8; nt++) {
        const int col = nhalf * 64 + nt * 8 + 2 * (l & 3);
        const float b0 = bv[col], b1 = bv[col + 1];
        float c0 = acc[nt][0], c1 = acc[nt][1], c2 = acc[nt][2], c3 = acc[nt][3];
        S1[0] += c0*c0 + c1*c1;  S2[0] += fabsf(c0) + fabsf(c1);  S3[0] += c0*b0 + c1*b1;
        S1[1] += c2*c2 + c3*c3;  S2[1] += fabsf(c2) + fabsf(c3);  S3[1] += c2*b0 + c3*b1;
    }
    #pragma unroll
    for (int r = 0; r < 2; r++) {
        S1[r] += __shfl_xor_sync(0xffffffffu, S1[r], 1);
        S1[r] += __shfl_xor_sync(0xffffffffu, S1[r], 2);
        S2[r] += __shfl_xor_sync(0xffffffffu, S2[r], 1);
        S2[r] += __shfl_xor_sync(0xffffffffu, S2[r], 2);
        S3[r] += __shfl_xor_sync(0xffffffffu, S3[r], 1);
        S3[r] += __shfl_xor_sync(0xffffffffu, S3[r], 2);
    }
    if ((l & 3) == 0) {
        const int r0 = mb + (l >> 2);
        sredS[r0][nhalf][0] = S1[0]; sredS[r0][nhalf][1] = S2[0]; sredS[r0][nhalf][2] = S3[0];
        sredS[r0 + 8][nhalf][0] = S1[1]; sredS[r0 + 8][nhalf][1] = S2[1]; sredS[r0 + 8][nhalf][2] = S3[1];
    }
    __syncthreads();

    float Pr[2], Qr[2];
    const float y2 = g_hb2s;
    const float maxn = (1.0f - 4e-3f) / sc;
    #pragma unroll
    for (int r = 0; r < 2; r++) {
        const int rl = mb + (l >> 2) + r * 8;
        float S1t = sredS[rl][0][0] + sredS[rl][1][0];
        float S2t = sredS[rl][0][1] + sredS[rl][1][1];
        float S3t = sredS[rl][0][2] + sredS[rl][1][2];
        float xn  = fmaxf(sqrtf(arow[rl]), 1e-15f);
        float mxn = fmaxf(sqrtf(S1t), 1e-15f);
        float at  = atanhf(fminf(sc * xn, 1.0f - 1e-7f));
        float s   = tanhf(mxn / xn * at) / (mxn * sc);
        if (S2t == 0.f) s = 0.f;
        float rn = fmaxf(sqrtf(s * s * S1t), 1e-15f);
        if (rn > maxn) s *= maxn / rn;          // proj before mobius_add
        float x2 = s * s * S1t;
        float xy = s * S3t;
        float Aa = 1.0f + 2.0f * c * xy + c * y2;
        float Bb2 = 1.0f - c * x2;
        float den = fmaxf(1.0f + 2.0f * c * xy + c * c * x2 * y2, 1e-15f);
        float P = Aa * s / den, Q = Bb2 / den;
        float h2 = P * P * S1t + 2.0f * P * Q * S3t + Q * Q * y2;
        float hn = fmaxf(sqrtf(h2), 1e-15f);
        if (hn > maxn) { float g = maxn / hn; P *= g; Q *= g; hn = maxn; }
        Pr[r] = P; Qr[r] = Q;
        if (((l & 3) == 0) && nhalf == 0) g_hn[rowbase + rl] = hn;
    }

    const int g0 = rowbase + mb + (l >> 2);
    #pragma unroll
    for (int nt = 0; nt < 8; nt++) {
        const int col = nhalf * 64 + nt * 8 + 2 * (l & 3);
        *(float2*)&g_h[(size_t)g0 * DOUT + col] =
            make_float2(Pr[0] * acc[nt][0] + Qr[0] * bv[col],
                        Pr[0] * acc[nt][1] + Qr[0] * bv[col + 1]);
        *(float2*)&g_h[(size_t)(g0 + 8) * DOUT + col] =
            make_float2(Pr[1] * acc[nt][2] + Qr[1] * bv[col],
                        Pr[1] * acc[nt][3] + Qr[1] * bv[col + 1]);
    }
}

// ============ FFMA GEMM tile config (K2) ============
#define BK  32
#define BMP 68
#define BN  128

// ---------------- K2: support = mobius_matvec(hw2, h) fused GEMM -> bf16 ----------------
__global__ __launch_bounds__(128) void k_sup_gemm(const float* __restrict__ cp) {
    __shared__ __align__(16) float pool[BK * BMP + BK * BN];
    __shared__ float par[64];
    float* As = pool;
    float* Bs = pool + BK * BMP;

    const int t = threadIdx.x;
    const int rowbase = blockIdx.x * 64;
    const float c  = cp[0];
    const float sc = sqrtf(c);

    const int tr = t >> 4, tc = t & 15;
    const int ar = t >> 3, ac = (t & 7) * 4;

    float acc[8][8];
    #pragma unroll
    for (int i = 0; i < 8; i++)
        #pragma unroll
        for (int j = 0; j < 8; j++) acc[i][j] = 0.f;

    float4 la[4], lb8[8];
    #pragma unroll
    for (int p = 0; p < 4; p++)
        la[p] = *(const float4*)&g_h[(size_t)(rowbase + p * 16 + ar) * DOUT + ac];
    #pragma unroll
    for (int f = 0; f < 8; f++)
        lb8[f] = *(const float4*)&g_hw2[t * DOUT + f * 4];

    const int ITERS = DOUT / BK;  // 4
    for (int it = 0; it < ITERS; ++it) {
        __syncthreads();
        #pragma unroll
        for (int p = 0; p < 4; p++) {
            float4 v = la[p]; int r = p * 16 + ar;
            As[(ac + 0) * BMP + r] = v.x; As[(ac + 1) * BMP + r] = v.y;
            As[(ac + 2) * BMP + r] = v.z; As[(ac + 3) * BMP + r] = v.w;
        }
        #pragma unroll
        for (int f = 0; f < 8; f++) {
            float4 v = lb8[f];
            Bs[(f * 4 + 0) * BN + t] = v.x; Bs[(f * 4 + 1) * BN + t] = v.y;
            Bs[(f * 4 + 2) * BN + t] = v.z; Bs[(f * 4 + 3) * BN + t] = v.w;
        }
        __syncthreads();
        if (it + 1 < ITERS) {
            int kt = (it + 1) * BK;
            #pragma unroll
            for (int p = 0; p < 4; p++)
                la[p] = *(const float4*)&g_h[(size_t)(rowbase + p * 16 + ar) * DOUT + kt + ac];
            #pragma unroll
            for (int f = 0; f < 8; f++)
                lb8[f] = *(const float4*)&g_hw2[t * DOUT + kt + f * 4];
        }
        #pragma unroll
        for (int kk = 0; kk < BK; kk++) {
            float4 a0 = *(const float4*)&As[kk * BMP + tr * 8];
            float4 a1 = *(const float4*)&As[kk * BMP + tr * 8 + 4];
            float4 b0 = *(const float4*)&Bs[kk * BN + tc * 4];
            float4 b1 = *(const float4*)&Bs[kk * BN + tc * 4 + 64];
            float av[8] = {a0.x,a0.y,a0.z,a0.w,a1.x,a1.y,a1.z,a1.w};
            float bv[8] = {b0.x,b0.y,b0.z,b0.w,b1.x,b1.y,b1.z,b1.w};
            #pragma unroll
            for (int i = 0; i < 8; i++)
                #pragma unroll
                for (int j = 0; j < 8; j++) acc[i][j] += av[i] * bv[j];
        }
    }
    __syncthreads();

    float* red = pool;  // [64][16][2]
    #pragma unroll
    for (int i = 0; i < 8; i++) {
        int r = tr * 8 + i;
        float p1 = 0.f, p2 = 0.f;
        #pragma unroll
        for (int j = 0; j < 8; j++) { float v = acc[i][j]; p1 += v * v; p2 += fabsf(v); }
        red[(r * 16 + tc) * 2 + 0] = p1;
        red[(r * 16 + tc) * 2 + 1] = p2;
    }
    __syncthreads();
    if (t < 64) {
        float S1 = 0.f, S2 = 0.f;
        #pragma unroll
        for (int q = 0; q < 16; q++) {
            S1 += red[(t * 16 + q) * 2 + 0];
            S2 += red[(t * 16 + q) * 2 + 1];
        }
        float hn  = g_hn[rowbase + t];
        float mxn = fmaxf(sqrtf(S1), 1e-15f);
        float at  = atanhf(fminf(sc * hn, 1.0f - 1e-7f));
        float s   = tanhf(mxn / hn * at) / (mxn * sc);
        if (S2 == 0.f) s = 0.f;
        par[t] = s;
    }
    __syncthreads();
    #pragma unroll
    for (int i = 0; i < 8; i++) {
        int r = tr * 8 + i;
        float s = par[r];
        uint32_t u0 = pack_bf16(s * acc[i][0], s * acc[i][1]);
        uint32_t u1 = pack_bf16(s * acc[i][2], s * acc[i][3]);
        uint32_t u2 = pack_bf16(s * acc[i][4], s * acc[i][5]);
        uint32_t u3 = pack_bf16(s * acc[i][6], s * acc[i][7]);
        *(uint2*)&g_supb[(size_t)(rowbase + r) * DOUT + tc * 4]      = make_uint2(u0, u1);
        *(uint2*)&g_supb[(size_t)(rowbase + r) * DOUT + 64 + tc * 4] = make_uint2(u2, u3);
    }
}

// ---------------- K3: bf16 mma.sync adj@sup + fused hyperbolic epilogue ----------------
// 128 CTAs x 512 threads (16 warps). CTA: M=64 x N=128, K=8192 chunked by KC=64.
// A path: cp.async fp32 3-stage ring (prefetch distance 2) -> in-smem bf16 convert.
// Uniform FIFO: exactly 2 commit groups per iter (may be empty) -> wait_group 2.
__global__ __launch_bounds__(512) void k_agg_mma(
    const float* __restrict__ adj, const float* __restrict__ bias,
    const float* __restrict__ cp, float* __restrict__ out)
{
    extern __shared__ __align__(16) char dsm[];
    char* Afp = dsm;                          // 3 x A32_BYTES fp32 stages
    char* Ab0 = dsm + 3 * A32_BYTES;          // single bf16 A buffer
    char* Bb0 = dsm + 3 * A32_BYTES + A_BYTES;// 2 x B_BYTES
    __shared__ float bv[128];
    __shared__ float arow[64];
    __shared__ float sredS[64][4][3];
    __shared__ float sredQ[64][4];

    const int t = threadIdx.x;
    const int w = t >> 5, l = t & 31;
    const int mb = (w & 3) * 16;      // warp m-band
    const int nq = w >> 2;            // warp n-quarter
    const int rowbase = blockIdx.x * 64;
    const float c  = cp[0];
    const float sc = sqrtf(c);

    if (t < 128) bv[t] = bias[t];

    // A loader/converter: 8 threads/row, 8 floats each
    const int arI = t >> 3, aq = t & 7;
    const float* aprow = adj + (size_t)(rowbase + arI) * NR;
    // B loader: 8 threads/k-row, 32 B each
    const int bkr = t >> 3, bq = t & 7;

    const uint32_t afpu  = smem_u32(Afp);
    const uint32_t abase = smem_u32(Ab0);
    const uint32_t bbase = smem_u32(Bb0);

    float acc[4][4];
    #pragma unroll
    for (int i = 0; i < 4; i++)
        #pragma unroll
        for (int j = 0; j < 4; j++) acc[i][j] = 0.f;

    float asq = 0.f;
    const int NCH = NR / KC;  // 128

    // -------- prologue: A(0)->stage0, A(1)->stage1, B(0)->buf0 (3 groups) --------
    #pragma unroll
    for (int i = 0; i < 2; i++)
        cp_async16(afpu + (uint32_t)((arI * KC + aq * 8 + i * 4) * 4),
                   aprow + aq * 8 + i * 4);
    CP_COMMIT();
    #pragma unroll
    for (int i = 0; i < 2; i++)
        cp_async16(afpu + (uint32_t)(A32_BYTES + (arI * KC + aq * 8 + i * 4) * 4),
                   aprow + KC + aq * 8 + i * 4);
    CP_COMMIT();
    #pragma unroll
    for (int i = 0; i < 2; i++)
        cp_async16(bbase + (uint32_t)(bkr * BSTR_B + bq * 32 + i * 16),
                   (const char*)g_supb + ((size_t)bkr * DOUT + bq * 16 + i * 8) * 2);
    CP_COMMIT();

    for (int ck = 0; ck < NCH; ++ck) {
        const int cur = ck & 1, nxt = cur ^ 1;
        // issue A(ck+2) into stage (ck+2)%3  (group may be empty)
        if (ck + 2 < NCH) {
            const uint32_t sb = afpu + (uint32_t)(((ck + 2) % 3) * A32_BYTES);
            #pragma unroll
            for (int i = 0; i < 2; i++)
                cp_async16(sb + (uint32_t)((arI * KC + aq * 8 + i * 4) * 4),
                           aprow + (ck + 2) * KC + aq * 8 + i * 4);
        }
        CP_COMMIT();
        // issue B(ck+1) into buf nxt (group may be empty)
        if (ck + 1 < NCH) {
            #pragma unroll
            for (int i = 0; i < 2; i++)
                cp_async16(bbase + (uint32_t)(nxt * B_BYTES + bkr * BSTR_B + bq * 32 + i * 16),
                           (const char*)g_supb + ((size_t)((ck + 1) * KC + bkr) * DOUT + bq * 16 + i * 8) * 2);
        }
        CP_COMMIT();
        CP_WAIT2();   // guarantees A(ck) [and A(ck+1)] + B(ck) complete

        // convert A(ck) fp32 stage -> bf16 A buffer; accumulate asq
        {
            const float* Sf = (const float*)(Afp + (ck % 3) * A32_BYTES) + arI * KC + aq * 8;
            float4 v0 = *(const float4*)(Sf);
            float4 v1 = *(const float4*)(Sf + 4);
            asq += v0.x*v0.x + v0.y*v0.y + v0.z*v0.z + v0.w*v0.w
                 + v1.x*v1.x + v1.y*v1.y + v1.z*v1.z + v1.w*v1.w;
            uint4 u = make_uint4(pack_bf16(v0.x, v0.y), pack_bf16(v0.z, v0.w),
                                 pack_bf16(v1.x, v1.y), pack_bf16(v1.z, v1.w));
            *(uint4*)&Ab0[arI * ASTR_B + aq * 16] = u;
        }
        __syncthreads();

        // MMA over bf16 A buffer + B buf cur
        {
            const uint32_t bT = bbase + (uint32_t)cur * B_BYTES;
            #pragma unroll
            for (int ks = 0; ks < 4; ks++) {
                uint32_t a0, a1, a2, a3;
                uint32_t aaddr = abase + (uint32_t)((mb + (l & 15)) * ASTR_B + ks * 32 + (l >> 4) * 16);
                LDSM_X4(a0, a1, a2, a3, aaddr);
                #pragma unroll
                for (int p = 0; p < 2; p++) {
                    uint32_t b0, b1, b2, b3;
                    uint32_t baddr = bT + (uint32_t)((ks * 16 + (l & 15)) * BSTR_B
                                   + nq * 64 + (2 * p + (l >> 4)) * 16);
                    LDSM_X4T(b0, b1, b2, b3, baddr);
                    mma_bf16(acc[2 * p],     a0, a1, a2, a3, b0, b1);
                    mma_bf16(acc[2 * p + 1], a0, a1, a2, a3, b2, b3);
                }
            }
        }
        __syncthreads();
    }

    // adj row sumsq: combine 8 loader threads per row
    asq += __shfl_xor_sync(0xffffffffu, asq, 1);
    asq += __shfl_xor_sync(0xffffffffu, asq, 2);
    asq += __shfl_xor_sync(0xffffffffu, asq, 4);
    if ((t & 7) == 0) arow[arI] = asq;
    __syncthreads();

    // fragment-domain hyperbolic epilogue (N split across 4 warp-quarters)
    float S1[2] = {0.f, 0.f}, S2[2] = {0.f, 0.f}, S3[2] = {0.f, 0.f};
    #pragma unroll
    for (int nt = 0; nt < 4; nt++) {
        const int col = nq * 32 + nt * 8 + 2 * (l & 3);
        const float b0 = bv[col], b1 = bv[col + 1];
        float c0 = acc[nt][0], c1 = acc[nt][1], c2 = acc[nt][2], c3 = acc[nt][3];
        S1[0] += c0*c0 + c1*c1;  S2[0] += fabsf(c0) + fabsf(c1);  S3[0] += c0*b0 + c1*b1;
        S1[1] += c2*c2 + c3*c3;  S2[1] += fabsf(c2) + fabsf(c3);  S3[1] += c2*b0 + c3*b1;
    }
    #pragma unroll
    for (int r = 0; r < 2; r++) {
        S1[r] += __shfl_xor_sync(0xffffffffu, S1[r], 1);
        S1[r] += __shfl_xor_sync(0xffffffffu, S1[r], 2);
        S2[r] += __shfl_xor_sync(0xffffffffu, S2[r], 1);
        S2[r] += __shfl_xor_sync(0xffffffffu, S2[r], 2);
        S3[r] += __shfl_xor_sync(0xffffffffu, S3[r], 1);
        S3[r] += __shfl_xor_sync(0xffffffffu, S3[r], 2);
    }
    if ((l & 3) == 0) {
        const int r0 = mb + (l >> 2);
        sredS[r0][nq][0] = S1[0]; sredS[r0][nq][1] = S2[0]; sredS[r0][nq][2] = S3[0];
        sredS[r0 + 8][nq][0] = S1[1]; sredS[r0 + 8][nq][1] = S2[1]; sredS[r0 + 8][nq][2] = S3[1];
    }
    __syncthreads();

    float Pr[2], Qr[2], Lr[2];
    const float y2 = g_b2s;
    const float maxn = (1.0f - 4e-3f) / sc;
    #pragma unroll
    for (int r = 0; r < 2; r++) {
        const int rl = mb + (l >> 2) + r * 8;
        float S1t = sredS[rl][0][0] + sredS[rl][1][0] + sredS[rl][2][0] + sredS[rl][3][0];
        float S2t = sredS[rl][0][1] + sredS[rl][1][1] + sredS[rl][2][1] + sredS[rl][3][1];
        float S3t = sredS[rl][0][2] + sredS[rl][1][2] + sredS[rl][2][2] + sredS[rl][3][2];
        float an  = fmaxf(sqrtf(arow[rl]), 1e-15f);
        float mxn = fmaxf(sqrtf(S1t), 1e-15f);
        float at  = atanhf(fminf(sc * an, 1.0f - 1e-7f));
        float s   = tanhf(mxn / an * at) / (mxn * sc);
        if (S2t == 0.f) s = 0.f;
        float x2 = s * s * S1t;
        float xy = s * S3t;
        float Aa = 1.0f + 2.0f * c * xy + c * y2;
        float Bb2 = 1.0f - c * x2;
        float den = fmaxf(1.0f + 2.0f * c * xy + c * c * x2 * y2, 1e-15f);
        float P = Aa * s / den, Q = Bb2 / den;
        float g2 = P * P * S1t + 2.0f * P * Q * S3t + Q * Q * y2;
        float gn = fmaxf(sqrtf(g2), 1e-15f);
        if (gn > maxn) { float g = maxn / gn; P *= g; Q *= g; gn = maxn; }
        Pr[r] = P; Qr[r] = Q;
        Lr[r] = atanhf(fminf(sc * gn, 1.0f - 1e-7f)) / (gn * sc);
    }

    float q2[2] = {0.f, 0.f};
    #pragma unroll
    for (int nt = 0; nt < 4; nt++) {
        const int col = nq * 32 + nt * 8 + 2 * (l & 3);
        const float b0 = bv[col], b1 = bv[col + 1];
        float v0 = Lr[0] * (Pr[0] * acc[nt][0] + Qr[0] * b0);
        float v1 = Lr[0] * (Pr[0] * acc[nt][1] + Qr[0] * b1);
        float v2 = Lr[1] * (Pr[1] * acc[nt][2] + Qr[1] * b0);
        float v3 = Lr[1] * (Pr[1] * acc[nt][3] + Qr[1] * b1);
        v0 = (v0 >= 0.f) ? v0 : 0.01f * v0;
        v1 = (v1 >= 0.f) ? v1 : 0.01f * v1;
        v2 = (v2 >= 0.f) ? v2 : 0.01f * v2;
        v3 = (v3 >= 0.f) ? v3 : 0.01f * v3;
        acc[nt][0] = v0; acc[nt][1] = v1; acc[nt][2] = v2; acc[nt][3] = v3;
        q2[0] += v0*v0 + v1*v1;
        q2[1] += v2*v2 + v3*v3;
    }
    #pragma unroll
    for (int r = 0; r < 2; r++) {
        q2[r] += __shfl_xor_sync(0xffffffffu, q2[r], 1);
        q2[r] += __shfl_xor_sync(0xffffffffu, q2[r], 2);
    }
    if ((l & 3) == 0) {
        const int r0 = mb + (l >> 2);
        sredQ[r0][nq] = q2[0];
        sredQ[r0 + 8][nq] = q2[1];
    }
    __syncthreads();

    float er[2];
    const float sc2 = sqrtf(1.0f - c);
    const float mn2 = (1.0f - 4e-3f) / sc2;
    #pragma unroll
    for (int r = 0; r < 2; r++) {
        const int rl = mb + (l >> 2) + r * 8;
        float q2t = sredQ[rl][0] + sredQ[rl][1] + sredQ[rl][2] + sredQ[rl][3];
        float un = fmaxf(sqrtf(q2t), 1e-15f);
        float e  = tanhf(sc * un) / (sc * un);      // expmap0 with curvature c
        float vn = fmaxf(sqrtf(e * e * q2t), 1e-15f);
        if (vn > mn2) e *= mn2 / vn;                // proj with curvature 1-c
        er[r] = e;
    }

    const int g0 = rowbase + mb + (l >> 2);
    #pragma unroll
    for (int nt = 0; nt < 4; nt++) {
        const int col = nq * 32 + nt * 8 + 2 * (l & 3);
        *(float2*)&out[(size_t)g0 * DOUT + col] =
            make_float2(er[0] * acc[nt][0], er[0] * acc[nt][1]);
        *(float2*)&out[(size_t)(g0 + 8) * DOUT + col] =
            make_float2(er[1] * acc[nt][2], er[1] * acc[nt][3]);
    }
}

// ---------------- launch ----------------
extern "C" void kernel_launch(void* const* d_in, const int* in_sizes, int n_in,
                              void* d_out, int out_size)
{
    const float* x   = (const float*)d_in[0];
    const float* adj = (const float*)d_in[1];
    const float* cp  = (const float*)d_in[2];
    const float* lw  = (const float*)d_in[3];
    const float* lb  = (const float*)d_in[4];
    const float* aw  = (const float*)d_in[5];
    const float* ab  = (const float*)d_in[6];
    float* out = (float*)d_out;

    cudaFuncSetAttribute(k_lin_mma, cudaFuncAttributeMaxDynamicSharedMemorySize, DYN_SMEM);
    cudaFuncSetAttribute(k_agg_mma, cudaFuncAttributeMaxDynamicSharedMemorySize, DYN3_SMEM);

    k_prep<<<2 * DOUT + 1, 128>>>(lw, lb, aw, ab, cp);
    k_lin_mma<<<NR / 64, 256, DYN_SMEM>>>(x, cp);
    k_sup_gemm<<<NR / 64, 128>>>(cp);
    k_agg_mma<<<NR / 64, 512, DYN3_SMEM>>>(adj, ab, cp, out);
}